// round 6
// baseline (speedup 1.0000x reference)
#include <cuda_runtime.h>
#include <cstdint>

typedef unsigned int u32;
typedef unsigned long long u64;
#define DEVINL __device__ __forceinline__

constexpr int F = 128, DIN = 64, D = 64, H = 8;

// smem byte offsets; 64-col bf16 arrays use stride 144B
constexpr u32 SB64 = 144;
constexpr u32 XH = 0;               // X hi  [128][64] (+pad)
constexpr u32 XL = 18432;           // X lo
constexpr u32 WH = 36864;           // W^T hi [64][64] (d-major rows, k=i)
constexpr u32 WL = 46080;           // W^T lo
constexpr u32 KH = 55296;           // K hi [128][64]
constexpr u32 KL = 73728;           // K lo
constexpr u32 GB = 92160;           // gamma[64] f32, beta[64] f32
constexpr u32 SMEM_TOTAL = 92672;

DEVINL u32 s2u(const void* p) {
    u32 a; asm("{ .reg .u64 t; cvta.to.shared.u64 t, %1; cvt.u32.u64 %0, t; }" : "=r"(a) : "l"(p));
    return a;
}
DEVINL void ldsm4(u32& r0, u32& r1, u32& r2, u32& r3, u32 a) {
    asm volatile("ldmatrix.sync.aligned.m8n8.x4.shared.b16 {%0,%1,%2,%3}, [%4];"
                 : "=r"(r0), "=r"(r1), "=r"(r2), "=r"(r3) : "r"(a));
}
DEVINL void ldsm4t(u32& r0, u32& r1, u32& r2, u32& r3, u32 a) {
    asm volatile("ldmatrix.sync.aligned.m8n8.x4.trans.shared.b16 {%0,%1,%2,%3}, [%4];"
                 : "=r"(r0), "=r"(r1), "=r"(r2), "=r"(r3) : "r"(a));
}
DEVINL void mma16816(float* c, u32 a0, u32 a1, u32 a2, u32 a3, u32 b0, u32 b1) {
    asm volatile("mma.sync.aligned.m16n8k16.row.col.f32.bf16.bf16.f32 "
                 "{%0,%1,%2,%3}, {%4,%5,%6,%7}, {%8,%9}, {%0,%1,%2,%3};"
                 : "+f"(c[0]), "+f"(c[1]), "+f"(c[2]), "+f"(c[3])
                 : "r"(a0), "r"(a1), "r"(a2), "r"(a3), "r"(b0), "r"(b1));
}
// pack two floats -> bf16x2 (x low half, y high half)
DEVINL u32 cvt2(float x, float y) {
    u32 r; asm("cvt.rn.bf16x2.f32 %0, %1, %2;" : "=r"(r) : "f"(y), "f"(x)); return r;
}
DEVINL void split2(float x, float y, u32& hi, u32& lo) {
    hi = cvt2(x, y);
    float rx = x - __uint_as_float(hi << 16);
    float ry = y - __uint_as_float(hi & 0xFFFF0000u);
    lo = cvt2(rx, ry);
}

struct Lane {
    int lr16, lh;   // A-ldsm addressing
    int bn, bk;     // B plain addressing
    int tg, td;     // B trans addressing
    int qr, qc;     // C fragment row/col
};

// 16(M)x64(N)x64(K) gemm: A rows f0.. at XHb/XLb (stride SB64), B [n][k] at WHb/WLb.
DEVINL void gemm_n64(float (*acc)[4], u32 sb, u32 XHb, u32 XLb, u32 WHb, u32 WLb,
                     int f0, const Lane& L) {
#pragma unroll
    for (int nt = 0; nt < 8; nt++)
#pragma unroll
        for (int j = 0; j < 4; j++) acc[nt][j] = 0.f;
#pragma unroll
    for (int ks = 0; ks < 4; ks++) {
        u32 aA = sb + (u32)((f0 + L.lr16) * SB64 + 32 * ks + L.lh * 16);
        u32 ah0, ah1, ah2, ah3, al0, al1, al2, al3;
        ldsm4(ah0, ah1, ah2, ah3, aA + XHb);
        ldsm4(al0, al1, al2, al3, aA + XLb);
#pragma unroll
        for (int n2 = 0; n2 < 4; n2++) {
            u32 aB = sb + (u32)((16 * n2 + L.bn) * SB64 + 32 * ks + L.bk * 16);
            u32 bh0, bh1, bh2, bh3, bl0, bl1, bl2, bl3;
            ldsm4(bh0, bh1, bh2, bh3, aB + WHb);
            ldsm4(bl0, bl1, bl2, bl3, aB + WLb);
            mma16816(acc[2 * n2],     ah0, ah1, ah2, ah3, bh0, bh1);
            mma16816(acc[2 * n2 + 1], ah0, ah1, ah2, ah3, bh2, bh3);
            mma16816(acc[2 * n2],     ah0, ah1, ah2, ah3, bl0, bl1);
            mma16816(acc[2 * n2 + 1], ah0, ah1, ah2, ah3, bl2, bl3);
            mma16816(acc[2 * n2],     al0, al1, al2, al3, bh0, bh1);
            mma16816(acc[2 * n2 + 1], al0, al1, al2, al3, bh2, bh3);
        }
    }
}

__global__ void __launch_bounds__(256, 2)
mha_hmma_kernel(const float* __restrict__ x,
                const float* __restrict__ wq,
                const float* __restrict__ wk,
                const float* __restrict__ wr,
                const float* __restrict__ gamma,
                const float* __restrict__ beta,
                float* __restrict__ out, int B) {
    extern __shared__ __align__(1024) char sm[];
    const u32 sb = s2u(sm);
    const int tid = threadIdx.x;
    const int w = tid >> 5, lane = tid & 31;
    const int h = blockIdx.x, b = blockIdx.y;
    const int f0 = w * 16;
    const size_t HBFD = (size_t)H * B * F * D;

    Lane L;
    L.lr16 = lane & 15; L.lh = lane >> 4;
    L.bn = (lane & 7) + ((lane >> 4) & 1) * 8; L.bk = (lane >> 3) & 1;
    L.tg = (lane & 7) + ((lane >> 3) & 1) * 8; L.td = ((lane >> 4) & 1) * 8;
    L.qr = lane >> 2; L.qc = (lane & 3) * 2;

    float* const gmS = (float*)(sm + GB);        // gamma[0..63], beta[64..127]
    if (tid < 128) gmS[tid] = (tid < 64) ? gamma[tid] : beta[tid - 64];

    // ---- X[b] -> bf16 hi/lo [f][i] ----
    {
        const float4* xg = (const float4*)(x + (size_t)b * F * DIN);
#pragma unroll
        for (int k = 0; k < 8; k++) {
            int idx4 = tid + 256 * k;
            int f = idx4 >> 4, i4 = (idx4 & 15) * 4;
            float4 v = xg[idx4];
            u32 h0, l0, h1, l1;
            split2(v.x, v.y, h0, l0);
            split2(v.z, v.w, h1, l1);
            u32 off = (u32)(f * SB64 + i4 * 2);
            *(uint2*)(sm + XH + off) = make_uint2(h0, h1);
            *(uint2*)(sm + XL + off) = make_uint2(l0, l1);
        }
    }

    // W loader (transpose to [d][i], split hi/lo)
    auto loadW = [&](const float* __restrict__ wp) {
#pragma unroll
        for (int it = 0; it < 8; it++) {
            int i = 2 * (4 * it + (tid >> 6));
            int d = tid & 63;
            float w0 = wp[i * (H * D) + h * D + d];
            float w1 = wp[(i + 1) * (H * D) + h * D + d];
            u32 hi, lo;
            split2(w0, w1, hi, lo);
            *(u32*)(sm + WH + d * SB64 + i * 2) = hi;
            *(u32*)(sm + WL + d * SB64 + i * 2) = lo;
        }
    };

    float acc[8][4];

    // ================= Q projection -> registers only =================
    loadW(wq);
    __syncthreads();
    gemm_n64(acc, sb, XH, XL, WH, WL, f0, L);
    // C fragment -> A fragment for S (k-chunk ks uses n-tiles 2ks, 2ks+1)
    u32 qfh[16], qfl[16];
#pragma unroll
    for (int ks = 0; ks < 4; ks++) {
        split2(acc[2 * ks][0],     acc[2 * ks][1],     qfh[4 * ks + 0], qfl[4 * ks + 0]);
        split2(acc[2 * ks][2],     acc[2 * ks][3],     qfh[4 * ks + 1], qfl[4 * ks + 1]);
        split2(acc[2 * ks + 1][0], acc[2 * ks + 1][1], qfh[4 * ks + 2], qfl[4 * ks + 2]);
        split2(acc[2 * ks + 1][2], acc[2 * ks + 1][3], qfh[4 * ks + 3], qfl[4 * ks + 3]);
    }
    __syncthreads();   // all W reads done

    // ================= K projection (V == K per reference) =================
    loadW(wk);
    __syncthreads();
    gemm_n64(acc, sb, XH, XL, WH, WL, f0, L);
#pragma unroll
    for (int nt = 0; nt < 8; nt++) {
        int c2 = (8 * nt + L.qc) * 2;
        int r1 = f0 + L.qr, r2 = r1 + 8;
        u32 hi, lo;
        split2(acc[nt][0], acc[nt][1], hi, lo);
        *(u32*)(sm + KH + r1 * SB64 + c2) = hi;
        *(u32*)(sm + KL + r1 * SB64 + c2) = lo;
        split2(acc[nt][2], acc[nt][3], hi, lo);
        *(u32*)(sm + KH + r2 * SB64 + c2) = hi;
        *(u32*)(sm + KL + r2 * SB64 + c2) = lo;
    }
    __syncthreads();   // K visible, W reads done

    // overlap Wr global loads with the S mma
    loadW(wr);

    // ================= S = Q K^T (A from regs, B = K smem) =================
    float sacc[16][4];
#pragma unroll
    for (int nt = 0; nt < 16; nt++)
#pragma unroll
        for (int j = 0; j < 4; j++) sacc[nt][j] = 0.f;
#pragma unroll
    for (int ks = 0; ks < 4; ks++) {
        u32 ah0 = qfh[4 * ks], ah1 = qfh[4 * ks + 1], ah2 = qfh[4 * ks + 2], ah3 = qfh[4 * ks + 3];
        u32 al0 = qfl[4 * ks], al1 = qfl[4 * ks + 1], al2 = qfl[4 * ks + 2], al3 = qfl[4 * ks + 3];
#pragma unroll
        for (int n2 = 0; n2 < 8; n2++) {
            u32 aB = sb + (u32)((16 * n2 + L.bn) * SB64 + 32 * ks + L.bk * 16);
            u32 bh0, bh1, bh2, bh3, bl0, bl1, bl2, bl3;
            ldsm4(bh0, bh1, bh2, bh3, aB + KH);
            ldsm4(bl0, bl1, bl2, bl3, aB + KL);
            mma16816(sacc[2 * n2],     ah0, ah1, ah2, ah3, bh0, bh1);
            mma16816(sacc[2 * n2 + 1], ah0, ah1, ah2, ah3, bh2, bh3);
            mma16816(sacc[2 * n2],     ah0, ah1, ah2, ah3, bl0, bl1);
            mma16816(sacc[2 * n2 + 1], ah0, ah1, ah2, ah3, bl2, bl3);
            mma16816(sacc[2 * n2],     al0, al1, al2, al3, bh0, bh1);
            mma16816(sacc[2 * n2 + 1], al0, al1, al2, al3, bh2, bh3);
        }
    }

    // ---- sigmoid(S/8) -> split bf16 A fragments in registers ----
    u32 afh[32], afl[32];
#pragma unroll
    for (int ks = 0; ks < 8; ks++) {
#pragma unroll
        for (int half = 0; half < 2; half++) {
            int nt = 2 * ks + half;
            float a0 = 1.0f / (1.0f + __expf(-0.125f * sacc[nt][0]));
            float a1 = 1.0f / (1.0f + __expf(-0.125f * sacc[nt][1]));
            float a2 = 1.0f / (1.0f + __expf(-0.125f * sacc[nt][2]));
            float a3 = 1.0f / (1.0f + __expf(-0.125f * sacc[nt][3]));
            split2(a0, a1, afh[4 * ks + 2 * half],     afl[4 * ks + 2 * half]);
            split2(a2, a3, afh[4 * ks + 2 * half + 1], afl[4 * ks + 2 * half + 1]);
        }
    }

    // ================= O = A * K (A from regs, B = K^T via ldsm.trans) =====
    float oc[8][4];
#pragma unroll
    for (int nt = 0; nt < 8; nt++)
#pragma unroll
        for (int j = 0; j < 4; j++) oc[nt][j] = 0.f;
#pragma unroll
    for (int ks = 0; ks < 8; ks++) {
        u32 ah0 = afh[4 * ks], ah1 = afh[4 * ks + 1], ah2 = afh[4 * ks + 2], ah3 = afh[4 * ks + 3];
        u32 al0 = afl[4 * ks], al1 = afl[4 * ks + 1], al2 = afl[4 * ks + 2], al3 = afl[4 * ks + 3];
#pragma unroll
        for (int n2 = 0; n2 < 4; n2++) {
            u32 aB = sb + (u32)((16 * ks + L.tg) * SB64 + (16 * n2 + L.td) * 2);
            u32 bh0, bh1, bh2, bh3, bl0, bl1, bl2, bl3;
            ldsm4t(bh0, bh1, bh2, bh3, aB + KH);
            ldsm4t(bl0, bl1, bl2, bl3, aB + KL);
            mma16816(oc[2 * n2],     ah0, ah1, ah2, ah3, bh0, bh1);
            mma16816(oc[2 * n2 + 1], ah0, ah1, ah2, ah3, bh2, bh3);
            mma16816(oc[2 * n2],     ah0, ah1, ah2, ah3, bl0, bl1);
            mma16816(oc[2 * n2 + 1], ah0, ah1, ah2, ah3, bl2, bl3);
            mma16816(oc[2 * n2],     al0, al1, al2, al3, bh0, bh1);
            mma16816(oc[2 * n2 + 1], al0, al1, al2, al3, bh2, bh3);
        }
    }

    // ---- LayerNorm rows + store out1 ----
    {
        float s1 = 0.f, q1 = 0.f, s2 = 0.f, q2 = 0.f;
#pragma unroll
        for (int nt = 0; nt < 8; nt++) {
            s1 += oc[nt][0] + oc[nt][1];
            q1 += oc[nt][0] * oc[nt][0] + oc[nt][1] * oc[nt][1];
            s2 += oc[nt][2] + oc[nt][3];
            q2 += oc[nt][2] * oc[nt][2] + oc[nt][3] * oc[nt][3];
        }
#pragma unroll
        for (int off = 1; off <= 2; off <<= 1) {
            s1 += __shfl_xor_sync(0xFFFFFFFFu, s1, off);
            q1 += __shfl_xor_sync(0xFFFFFFFFu, q1, off);
            s2 += __shfl_xor_sync(0xFFFFFFFFu, s2, off);
            q2 += __shfl_xor_sync(0xFFFFFFFFu, q2, off);
        }
        float mu1 = s1 * (1.0f / 64.0f);
        float v1 = q1 * (1.0f / 64.0f) - mu1 * mu1;
        float sc1 = rsqrtf(v1 + 1e-3f);
        float mu2 = s2 * (1.0f / 64.0f);
        float v2 = q2 * (1.0f / 64.0f) - mu2 * mu2;
        float sc2 = rsqrtf(v2 + 1e-3f);

        float* o1 = out + ((size_t)h * B + b) * (F * D);
        int r1 = f0 + L.qr, r2 = r1 + 8;
#pragma unroll
        for (int nt = 0; nt < 8; nt++) {
            int c = 8 * nt + L.qc;
            float g0 = gmS[c], g1 = gmS[c + 1];
            float b0 = gmS[64 + c], b1 = gmS[64 + c + 1];
            float2 v;
            v.x = (oc[nt][0] - mu1) * sc1 * g0 + b0;
            v.y = (oc[nt][1] - mu1) * sc1 * g1 + b1;
            *(float2*)(o1 + r1 * 64 + c) = v;
            v.x = (oc[nt][2] - mu2) * sc2 * g0 + b0;
            v.y = (oc[nt][3] - mu2) * sc2 * g1 + b1;
            *(float2*)(o1 + r2 * 64 + c) = v;
        }
    }
    __syncthreads();   // Wr visible

    // ================= R projection -> direct STG =================
    gemm_n64(acc, sb, XH, XL, WH, WL, f0, L);
    {
        float* o2 = out + HBFD + ((size_t)h * B + b) * (F * D);
#pragma unroll
        for (int nt = 0; nt < 8; nt++) {
            int c = 8 * nt + L.qc;
            int r1 = f0 + L.qr, r2 = r1 + 8;
            *(float2*)(o2 + r1 * 64 + c) = make_float2(acc[nt][0], acc[nt][1]);
            *(float2*)(o2 + r2 * 64 + c) = make_float2(acc[nt][2], acc[nt][3]);
        }
    }
}

extern "C" void kernel_launch(void* const* d_in, const int* in_sizes, int n_in,
                              void* d_out, int out_size) {
    const float* x     = (const float*)d_in[0];
    const float* wq    = (const float*)d_in[1];
    const float* wk    = (const float*)d_in[2];
    const float* wr    = (const float*)d_in[3];
    const float* gamma = (const float*)d_in[4];
    const float* beta  = (const float*)d_in[5];
    float* out = (float*)d_out;

    int B = in_sizes[0] / (F * DIN);

    cudaFuncSetAttribute(mha_hmma_kernel,
                         cudaFuncAttributeMaxDynamicSharedMemorySize, SMEM_TOTAL);

    dim3 grid(H, B);
    mha_hmma_kernel<<<grid, 256, SMEM_TOTAL>>>(x, wq, wk, wr, gamma, beta, out, B);
}

// round 7
// speedup vs baseline: 1.5876x; 1.5876x over previous
#include <cuda_runtime.h>
#include <cstdint>

typedef unsigned int u32;
typedef unsigned long long u64;
#define DEVINL __device__ __forceinline__

constexpr int F = 128, DIN = 64, D = 64, H = 8;

// smem byte offsets; 64-col bf16 arrays use stride 144B
constexpr u32 SB64 = 144;
constexpr u32 XH = 0;               // X hi  [128][64] (+pad)
constexpr u32 XL = 18432;           // X lo
constexpr u32 WH = 36864;           // W^T hi [64][64] (d-major rows, k=i)
constexpr u32 WL = 46080;           // W^T lo
constexpr u32 KH = 55296;           // K hi [128][64]
constexpr u32 KL = 73728;           // K lo
constexpr u32 GB = 92160;           // gamma[64] f32, beta[64] f32
constexpr u32 SMEM_TOTAL = 92672;

DEVINL u32 s2u(const void* p) {
    u32 a; asm("{ .reg .u64 t; cvta.to.shared.u64 t, %1; cvt.u32.u64 %0, t; }" : "=r"(a) : "l"(p));
    return a;
}
DEVINL void ldsm4(u32& r0, u32& r1, u32& r2, u32& r3, u32 a) {
    asm volatile("ldmatrix.sync.aligned.m8n8.x4.shared.b16 {%0,%1,%2,%3}, [%4];"
                 : "=r"(r0), "=r"(r1), "=r"(r2), "=r"(r3) : "r"(a));
}
DEVINL void ldsm4t(u32& r0, u32& r1, u32& r2, u32& r3, u32 a) {
    asm volatile("ldmatrix.sync.aligned.m8n8.x4.trans.shared.b16 {%0,%1,%2,%3}, [%4];"
                 : "=r"(r0), "=r"(r1), "=r"(r2), "=r"(r3) : "r"(a));
}
DEVINL void mma16816(float* c, u32 a0, u32 a1, u32 a2, u32 a3, u32 b0, u32 b1) {
    asm volatile("mma.sync.aligned.m16n8k16.row.col.f32.bf16.bf16.f32 "
                 "{%0,%1,%2,%3}, {%4,%5,%6,%7}, {%8,%9}, {%0,%1,%2,%3};"
                 : "+f"(c[0]), "+f"(c[1]), "+f"(c[2]), "+f"(c[3])
                 : "r"(a0), "r"(a1), "r"(a2), "r"(a3), "r"(b0), "r"(b1));
}
// pack two floats -> bf16x2 (x low half, y high half)
DEVINL u32 cvt2(float x, float y) {
    u32 r; asm("cvt.rn.bf16x2.f32 %0, %1, %2;" : "=r"(r) : "f"(y), "f"(x)); return r;
}
DEVINL void split2(float x, float y, u32& hi, u32& lo) {
    hi = cvt2(x, y);
    float rx = x - __uint_as_float(hi << 16);
    float ry = y - __uint_as_float(hi & 0xFFFF0000u);
    lo = cvt2(rx, ry);
}

struct Lane {
    int lr16, lh;   // A-ldsm addressing
    int bn, bk;     // B plain addressing
    int tg, td;     // B trans addressing
    int qr, qc;     // C fragment row/col
};

// 16(M)x64(N)x64(K) gemm: A rows f0.. at XHb/XLb (stride SB64), B [n][k] at WHb/WLb.
DEVINL void gemm_n64(float (*acc)[4], u32 sb, u32 XHb, u32 XLb, u32 WHb, u32 WLb,
                     int f0, const Lane& L) {
#pragma unroll
    for (int nt = 0; nt < 8; nt++)
#pragma unroll
        for (int j = 0; j < 4; j++) acc[nt][j] = 0.f;
#pragma unroll
    for (int ks = 0; ks < 4; ks++) {
        u32 aA = sb + (u32)((f0 + L.lr16) * SB64 + 32 * ks + L.lh * 16);
        u32 ah0, ah1, ah2, ah3, al0, al1, al2, al3;
        ldsm4(ah0, ah1, ah2, ah3, aA + XHb);
        ldsm4(al0, al1, al2, al3, aA + XLb);
#pragma unroll
        for (int n2 = 0; n2 < 4; n2++) {
            u32 aB = sb + (u32)((16 * n2 + L.bn) * SB64 + 32 * ks + L.bk * 16);
            u32 bh0, bh1, bh2, bh3, bl0, bl1, bl2, bl3;
            ldsm4(bh0, bh1, bh2, bh3, aB + WHb);
            ldsm4(bl0, bl1, bl2, bl3, aB + WLb);
            mma16816(acc[2 * n2],     ah0, ah1, ah2, ah3, bh0, bh1);
            mma16816(acc[2 * n2 + 1], ah0, ah1, ah2, ah3, bh2, bh3);
            mma16816(acc[2 * n2],     ah0, ah1, ah2, ah3, bl0, bl1);
            mma16816(acc[2 * n2 + 1], ah0, ah1, ah2, ah3, bl2, bl3);
            mma16816(acc[2 * n2],     al0, al1, al2, al3, bh0, bh1);
            mma16816(acc[2 * n2 + 1], al0, al1, al2, al3, bh2, bh3);
        }
    }
}

__global__ void __launch_bounds__(256, 2)
mha_hmma_kernel(const float* __restrict__ x,
                const float* __restrict__ wq,
                const float* __restrict__ wk,
                const float* __restrict__ wr,
                const float* __restrict__ gamma,
                const float* __restrict__ beta,
                float* __restrict__ out, int B) {
    extern __shared__ __align__(1024) char sm[];
    const u32 sb = s2u(sm);
    const int tid = threadIdx.x;
    const int w = tid >> 5, lane = tid & 31;
    const int h = blockIdx.x, b = blockIdx.y;
    const int f0 = w * 16;
    const size_t HBFD = (size_t)H * B * F * D;

    Lane L;
    L.lr16 = lane & 15; L.lh = lane >> 4;
    L.bn = (lane & 7) + ((lane >> 4) & 1) * 8; L.bk = (lane >> 3) & 1;
    L.tg = (lane & 7) + ((lane >> 3) & 1) * 8; L.td = ((lane >> 4) & 1) * 8;
    L.qr = lane >> 2; L.qc = (lane & 3) * 2;

    float* const gmS = (float*)(sm + GB);        // gamma[0..63], beta[64..127]
    if (tid < 128) gmS[tid] = (tid < 64) ? gamma[tid] : beta[tid - 64];

    // ---- X[b] -> bf16 hi/lo [f][i] ----
    {
        const float4* xg = (const float4*)(x + (size_t)b * F * DIN);
#pragma unroll
        for (int k = 0; k < 8; k++) {
            int idx4 = tid + 256 * k;
            int f = idx4 >> 4, i4 = (idx4 & 15) * 4;
            float4 v = xg[idx4];
            u32 h0, l0, h1, l1;
            split2(v.x, v.y, h0, l0);
            split2(v.z, v.w, h1, l1);
            u32 off = (u32)(f * SB64 + i4 * 2);
            *(uint2*)(sm + XH + off) = make_uint2(h0, h1);
            *(uint2*)(sm + XL + off) = make_uint2(l0, l1);
        }
    }

    // W loader (transpose to [d][i], split hi/lo)
    auto loadW = [&](const float* __restrict__ wp) {
#pragma unroll
        for (int it = 0; it < 8; it++) {
            int i = 2 * (4 * it + (tid >> 6));
            int d = tid & 63;
            float w0 = wp[i * (H * D) + h * D + d];
            float w1 = wp[(i + 1) * (H * D) + h * D + d];
            u32 hi, lo;
            split2(w0, w1, hi, lo);
            *(u32*)(sm + WH + d * SB64 + i * 2) = hi;
            *(u32*)(sm + WL + d * SB64 + i * 2) = lo;
        }
    };

    float acc[8][4];

    // ================= Q projection -> registers only =================
    loadW(wq);
    __syncthreads();
    gemm_n64(acc, sb, XH, XL, WH, WL, f0, L);
    // C fragment -> A fragment for S (k-chunk ks uses n-tiles 2ks, 2ks+1)
    u32 qfh[16], qfl[16];
#pragma unroll
    for (int ks = 0; ks < 4; ks++) {
        split2(acc[2 * ks][0],     acc[2 * ks][1],     qfh[4 * ks + 0], qfl[4 * ks + 0]);
        split2(acc[2 * ks][2],     acc[2 * ks][3],     qfh[4 * ks + 1], qfl[4 * ks + 1]);
        split2(acc[2 * ks + 1][0], acc[2 * ks + 1][1], qfh[4 * ks + 2], qfl[4 * ks + 2]);
        split2(acc[2 * ks + 1][2], acc[2 * ks + 1][3], qfh[4 * ks + 3], qfl[4 * ks + 3]);
    }
    __syncthreads();   // all W reads done

    // ================= K projection (V == K per reference) =================
    loadW(wk);
    __syncthreads();
    gemm_n64(acc, sb, XH, XL, WH, WL, f0, L);
#pragma unroll
    for (int nt = 0; nt < 8; nt++) {
        int c2 = (8 * nt + L.qc) * 2;
        int r1 = f0 + L.qr, r2 = r1 + 8;
        u32 hi, lo;
        split2(acc[nt][0], acc[nt][1], hi, lo);
        *(u32*)(sm + KH + r1 * SB64 + c2) = hi;
        *(u32*)(sm + KL + r1 * SB64 + c2) = lo;
        split2(acc[nt][2], acc[nt][3], hi, lo);
        *(u32*)(sm + KH + r2 * SB64 + c2) = hi;
        *(u32*)(sm + KL + r2 * SB64 + c2) = lo;
    }
    __syncthreads();   // K visible, W reads done

    // overlap Wr global loads with the S/O phase
    loadW(wr);

    // ============ fused S -> sigmoid -> O, by 64-column g-halves ============
    float oc[8][4];
#pragma unroll
    for (int nt = 0; nt < 8; nt++)
#pragma unroll
        for (int j = 0; j < 4; j++) oc[nt][j] = 0.f;

#pragma unroll
    for (int hb = 0; hb < 2; hb++) {
        // ---- S half: rows f0..f0+15, cols g in [64*hb, 64*hb+64) ----
        float sacc[8][4];
#pragma unroll
        for (int nt = 0; nt < 8; nt++)
#pragma unroll
            for (int j = 0; j < 4; j++) sacc[nt][j] = 0.f;
#pragma unroll
        for (int ks = 0; ks < 4; ks++) {
            u32 ah0 = qfh[4 * ks], ah1 = qfh[4 * ks + 1], ah2 = qfh[4 * ks + 2], ah3 = qfh[4 * ks + 3];
            u32 al0 = qfl[4 * ks], al1 = qfl[4 * ks + 1], al2 = qfl[4 * ks + 2], al3 = qfl[4 * ks + 3];
#pragma unroll
            for (int n2 = 0; n2 < 4; n2++) {
                u32 aB = sb + (u32)((16 * (4 * hb + n2) + L.bn) * SB64 + 32 * ks + L.bk * 16);
                u32 bh0, bh1, bh2, bh3, bl0, bl1, bl2, bl3;
                ldsm4(bh0, bh1, bh2, bh3, aB + KH);
                ldsm4(bl0, bl1, bl2, bl3, aB + KL);
                mma16816(sacc[2 * n2],     ah0, ah1, ah2, ah3, bh0, bh1);
                mma16816(sacc[2 * n2 + 1], ah0, ah1, ah2, ah3, bh2, bh3);
                mma16816(sacc[2 * n2],     ah0, ah1, ah2, ah3, bl0, bl1);
                mma16816(sacc[2 * n2 + 1], ah0, ah1, ah2, ah3, bl2, bl3);
                mma16816(sacc[2 * n2],     al0, al1, al2, al3, bh0, bh1);
                mma16816(sacc[2 * n2 + 1], al0, al1, al2, al3, bh2, bh3);
            }
        }

        // ---- sigmoid chunk (16 g) -> O k-step, fragments die immediately ----
#pragma unroll
        for (int ks2 = 0; ks2 < 4; ks2++) {
            u32 afh[4], afl[4];
#pragma unroll
            for (int half = 0; half < 2; half++) {
                int nt = 2 * ks2 + half;
                float a0 = 1.0f / (1.0f + __expf(-0.125f * sacc[nt][0]));
                float a1 = 1.0f / (1.0f + __expf(-0.125f * sacc[nt][1]));
                float a2 = 1.0f / (1.0f + __expf(-0.125f * sacc[nt][2]));
                float a3 = 1.0f / (1.0f + __expf(-0.125f * sacc[nt][3]));
                split2(a0, a1, afh[2 * half],     afl[2 * half]);
                split2(a2, a3, afh[2 * half + 1], afl[2 * half + 1]);
            }
#pragma unroll
            for (int n2 = 0; n2 < 4; n2++) {
                u32 aB = sb + (u32)((16 * (4 * hb + ks2) + L.tg) * SB64 + (16 * n2 + L.td) * 2);
                u32 bh0, bh1, bh2, bh3, bl0, bl1, bl2, bl3;
                ldsm4t(bh0, bh1, bh2, bh3, aB + KH);
                ldsm4t(bl0, bl1, bl2, bl3, aB + KL);
                mma16816(oc[2 * n2],     afh[0], afh[1], afh[2], afh[3], bh0, bh1);
                mma16816(oc[2 * n2 + 1], afh[0], afh[1], afh[2], afh[3], bh2, bh3);
                mma16816(oc[2 * n2],     afh[0], afh[1], afh[2], afh[3], bl0, bl1);
                mma16816(oc[2 * n2 + 1], afh[0], afh[1], afh[2], afh[3], bl2, bl3);
                mma16816(oc[2 * n2],     afl[0], afl[1], afl[2], afl[3], bh0, bh1);
                mma16816(oc[2 * n2 + 1], afl[0], afl[1], afl[2], afl[3], bh2, bh3);
            }
        }
    }

    // ---- LayerNorm rows + store out1 ----
    {
        float s1 = 0.f, q1 = 0.f, s2 = 0.f, q2 = 0.f;
#pragma unroll
        for (int nt = 0; nt < 8; nt++) {
            s1 += oc[nt][0] + oc[nt][1];
            q1 += oc[nt][0] * oc[nt][0] + oc[nt][1] * oc[nt][1];
            s2 += oc[nt][2] + oc[nt][3];
            q2 += oc[nt][2] * oc[nt][2] + oc[nt][3] * oc[nt][3];
        }
#pragma unroll
        for (int off = 1; off <= 2; off <<= 1) {
            s1 += __shfl_xor_sync(0xFFFFFFFFu, s1, off);
            q1 += __shfl_xor_sync(0xFFFFFFFFu, q1, off);
            s2 += __shfl_xor_sync(0xFFFFFFFFu, s2, off);
            q2 += __shfl_xor_sync(0xFFFFFFFFu, q2, off);
        }
        float mu1 = s1 * (1.0f / 64.0f);
        float v1 = q1 * (1.0f / 64.0f) - mu1 * mu1;
        float sc1 = rsqrtf(v1 + 1e-3f);
        float mu2 = s2 * (1.0f / 64.0f);
        float v2 = q2 * (1.0f / 64.0f) - mu2 * mu2;
        float sc2 = rsqrtf(v2 + 1e-3f);

        float* o1 = out + ((size_t)h * B + b) * (F * D);
        int r1 = f0 + L.qr, r2 = r1 + 8;
#pragma unroll
        for (int nt = 0; nt < 8; nt++) {
            int c = 8 * nt + L.qc;
            float g0 = gmS[c], g1 = gmS[c + 1];
            float b0 = gmS[64 + c], b1 = gmS[64 + c + 1];
            float2 v;
            v.x = (oc[nt][0] - mu1) * sc1 * g0 + b0;
            v.y = (oc[nt][1] - mu1) * sc1 * g1 + b1;
            *(float2*)(o1 + r1 * 64 + c) = v;
            v.x = (oc[nt][2] - mu2) * sc2 * g0 + b0;
            v.y = (oc[nt][3] - mu2) * sc2 * g1 + b1;
            *(float2*)(o1 + r2 * 64 + c) = v;
        }
    }
    __syncthreads();   // Wr visible

    // ================= R projection -> direct STG =================
    gemm_n64(acc, sb, XH, XL, WH, WL, f0, L);
    {
        float* o2 = out + HBFD + ((size_t)h * B + b) * (F * D);
#pragma unroll
        for (int nt = 0; nt < 8; nt++) {
            int c = 8 * nt + L.qc;
            int r1 = f0 + L.qr, r2 = r1 + 8;
            *(float2*)(o2 + r1 * 64 + c) = make_float2(acc[nt][0], acc[nt][1]);
            *(float2*)(o2 + r2 * 64 + c) = make_float2(acc[nt][2], acc[nt][3]);
        }
    }
}

extern "C" void kernel_launch(void* const* d_in, const int* in_sizes, int n_in,
                              void* d_out, int out_size) {
    const float* x     = (const float*)d_in[0];
    const float* wq    = (const float*)d_in[1];
    const float* wk    = (const float*)d_in[2];
    const float* wr    = (const float*)d_in[3];
    const float* gamma = (const float*)d_in[4];
    const float* beta  = (const float*)d_in[5];
    float* out = (float*)d_out;

    int B = in_sizes[0] / (F * DIN);

    cudaFuncSetAttribute(mha_hmma_kernel,
                         cudaFuncAttributeMaxDynamicSharedMemorySize, SMEM_TOTAL);

    dim3 grid(H, B);
    mha_hmma_kernel<<<grid, 256, SMEM_TOTAL>>>(x, wq, wk, wr, gamma, beta, out, B);
}

// round 8
// speedup vs baseline: 1.6963x; 1.0685x over previous
#include <cuda_runtime.h>
#include <cstdint>

typedef unsigned int u32;
typedef unsigned long long u64;
#define DEVINL __device__ __forceinline__

constexpr int F = 128, DIN = 64, D = 64, H = 8;

// smem byte offsets; 64-col bf16 arrays use stride 144B
constexpr u32 SB64 = 144;
// X stage aliased with K (X fragments are captured to regs before K is stored)
constexpr u32 KH = 0;               // X hi, later K hi   [128][64] (+pad)
constexpr u32 KL = 18432;           // X lo, later K lo
constexpr u32 WQH = 36864, WQL = 46080;   // Wq^T hi/lo [64][64] (d rows, k=i)
constexpr u32 WKH = 55296, WKL = 64512;   // Wk^T hi/lo
constexpr u32 WRH = 73728, WRL = 82944;   // Wr^T hi/lo
constexpr u32 GB = 92160;           // gamma[64] f32, beta[64] f32
constexpr u32 SMEM_TOTAL = 92672;

DEVINL u32 s2u(const void* p) {
    u32 a; asm("{ .reg .u64 t; cvta.to.shared.u64 t, %1; cvt.u32.u64 %0, t; }" : "=r"(a) : "l"(p));
    return a;
}
DEVINL void ldsm4(u32& r0, u32& r1, u32& r2, u32& r3, u32 a) {
    asm volatile("ldmatrix.sync.aligned.m8n8.x4.shared.b16 {%0,%1,%2,%3}, [%4];"
                 : "=r"(r0), "=r"(r1), "=r"(r2), "=r"(r3) : "r"(a));
}
DEVINL void ldsm4t(u32& r0, u32& r1, u32& r2, u32& r3, u32 a) {
    asm volatile("ldmatrix.sync.aligned.m8n8.x4.trans.shared.b16 {%0,%1,%2,%3}, [%4];"
                 : "=r"(r0), "=r"(r1), "=r"(r2), "=r"(r3) : "r"(a));
}
DEVINL void mma16816(float* c, u32 a0, u32 a1, u32 a2, u32 a3, u32 b0, u32 b1) {
    asm volatile("mma.sync.aligned.m16n8k16.row.col.f32.bf16.bf16.f32 "
                 "{%0,%1,%2,%3}, {%4,%5,%6,%7}, {%8,%9}, {%0,%1,%2,%3};"
                 : "+f"(c[0]), "+f"(c[1]), "+f"(c[2]), "+f"(c[3])
                 : "r"(a0), "r"(a1), "r"(a2), "r"(a3), "r"(b0), "r"(b1));
}
// pack two floats -> bf16x2 (x low half, y high half)
DEVINL u32 cvt2(float x, float y) {
    u32 r; asm("cvt.rn.bf16x2.f32 %0, %1, %2;" : "=r"(r) : "f"(y), "f"(x)); return r;
}
DEVINL void split2(float x, float y, u32& hi, u32& lo) {
    hi = cvt2(x, y);
    float rx = x - __uint_as_float(hi << 16);
    float ry = y - __uint_as_float(hi & 0xFFFF0000u);
    lo = cvt2(rx, ry);
}

struct Lane {
    int lr16, lh;   // A-ldsm addressing
    int bn, bk;     // B plain addressing
    int tg, td;     // B trans addressing
    int qr, qc;     // C fragment row/col
};

// 16x64x64 projection with A-fragments in registers (3-term split).
DEVINL void proj3(float (*acc)[4], u32 sb, u32 WHb, u32 WLb,
                  const u32* xfh, const u32* xfl, const Lane& L) {
#pragma unroll
    for (int nt = 0; nt < 8; nt++)
#pragma unroll
        for (int j = 0; j < 4; j++) acc[nt][j] = 0.f;
#pragma unroll
    for (int ks = 0; ks < 4; ks++) {
        u32 ah0 = xfh[4 * ks], ah1 = xfh[4 * ks + 1], ah2 = xfh[4 * ks + 2], ah3 = xfh[4 * ks + 3];
        u32 al0 = xfl[4 * ks], al1 = xfl[4 * ks + 1], al2 = xfl[4 * ks + 2], al3 = xfl[4 * ks + 3];
#pragma unroll
        for (int n2 = 0; n2 < 4; n2++) {
            u32 aB = sb + (u32)((16 * n2 + L.bn) * SB64 + 32 * ks + L.bk * 16);
            u32 bh0, bh1, bh2, bh3, bl0, bl1, bl2, bl3;
            ldsm4(bh0, bh1, bh2, bh3, aB + WHb);
            ldsm4(bl0, bl1, bl2, bl3, aB + WLb);
            mma16816(acc[2 * n2],     ah0, ah1, ah2, ah3, bh0, bh1);
            mma16816(acc[2 * n2 + 1], ah0, ah1, ah2, ah3, bh2, bh3);
            mma16816(acc[2 * n2],     ah0, ah1, ah2, ah3, bl0, bl1);
            mma16816(acc[2 * n2 + 1], ah0, ah1, ah2, ah3, bl2, bl3);
            mma16816(acc[2 * n2],     al0, al1, al2, al3, bh0, bh1);
            mma16816(acc[2 * n2 + 1], al0, al1, al2, al3, bh2, bh3);
        }
    }
}

__global__ void __launch_bounds__(256, 2)
mha_hmma_kernel(const float* __restrict__ x,
                const float* __restrict__ wq,
                const float* __restrict__ wk,
                const float* __restrict__ wr,
                const float* __restrict__ gamma,
                const float* __restrict__ beta,
                float* __restrict__ out, int B) {
    extern __shared__ __align__(1024) char sm[];
    const u32 sb = s2u(sm);
    const int tid = threadIdx.x;
    const int w = tid >> 5, lane = tid & 31;
    const int h = blockIdx.x, b = blockIdx.y;
    const int f0 = w * 16;
    const size_t HBFD = (size_t)H * B * F * D;

    Lane L;
    L.lr16 = lane & 15; L.lh = lane >> 4;
    L.bn = (lane & 7) + ((lane >> 4) & 1) * 8; L.bk = (lane >> 3) & 1;
    L.tg = (lane & 7) + ((lane >> 3) & 1) * 8; L.td = ((lane >> 4) & 1) * 8;
    L.qr = lane >> 2; L.qc = (lane & 3) * 2;

    float* const gmS = (float*)(sm + GB);        // gamma[0..63], beta[64..127]
    if (tid < 128) gmS[tid] = (tid < 64) ? gamma[tid] : beta[tid - 64];

    // ---- X[b] -> bf16 hi/lo [f][i] into the (future K) region ----
    {
        const float4* xg = (const float4*)(x + (size_t)b * F * DIN);
#pragma unroll
        for (int k = 0; k < 8; k++) {
            int idx4 = tid + 256 * k;
            int f = idx4 >> 4, i4 = (idx4 & 15) * 4;
            float4 v = xg[idx4];
            u32 h0, l0, h1, l1;
            split2(v.x, v.y, h0, l0);
            split2(v.z, v.w, h1, l1);
            u32 off = (u32)(f * SB64 + i4 * 2);
            *(uint2*)(sm + KH + off) = make_uint2(h0, h1);
            *(uint2*)(sm + KL + off) = make_uint2(l0, l1);
        }
    }

    // ---- all three W's upfront (transpose to [d][i], split hi/lo) ----
    auto loadW = [&](const float* __restrict__ wp, u32 WHb, u32 WLb) {
#pragma unroll
        for (int it = 0; it < 8; it++) {
            int i = 2 * (4 * it + (tid >> 6));
            int d = tid & 63;
            float w0 = wp[i * (H * D) + h * D + d];
            float w1 = wp[(i + 1) * (H * D) + h * D + d];
            u32 hi, lo;
            split2(w0, w1, hi, lo);
            *(u32*)(sm + WHb + d * SB64 + i * 2) = hi;
            *(u32*)(sm + WLb + d * SB64 + i * 2) = lo;
        }
    };
    loadW(wq, WQH, WQL);
    loadW(wk, WKH, WKL);
    loadW(wr, WRH, WRL);
    __syncthreads();

    // ---- capture X A-fragments to registers (once, reused by 3 projections) ----
    u32 xfh[16], xfl[16];
#pragma unroll
    for (int ks = 0; ks < 4; ks++) {
        u32 aA = sb + (u32)((f0 + L.lr16) * SB64 + 32 * ks + L.lh * 16);
        ldsm4(xfh[4 * ks], xfh[4 * ks + 1], xfh[4 * ks + 2], xfh[4 * ks + 3], aA + KH);
        ldsm4(xfl[4 * ks], xfl[4 * ks + 1], xfl[4 * ks + 2], xfl[4 * ks + 3], aA + KL);
    }
    __syncthreads();   // all warps captured X; K region may now be overwritten

    float acc[8][4];

    // ================= Q projection -> qf registers =================
    proj3(acc, sb, WQH, WQL, xfh, xfl, L);
    u32 qfh[16], qfl[16];
#pragma unroll
    for (int ks = 0; ks < 4; ks++) {
        split2(acc[2 * ks][0],     acc[2 * ks][1],     qfh[4 * ks + 0], qfl[4 * ks + 0]);
        split2(acc[2 * ks][2],     acc[2 * ks][3],     qfh[4 * ks + 1], qfl[4 * ks + 1]);
        split2(acc[2 * ks + 1][0], acc[2 * ks + 1][1], qfh[4 * ks + 2], qfl[4 * ks + 2]);
        split2(acc[2 * ks + 1][2], acc[2 * ks + 1][3], qfh[4 * ks + 3], qfl[4 * ks + 3]);
    }

    // ================= R projection -> direct STG =================
    proj3(acc, sb, WRH, WRL, xfh, xfl, L);
    {
        float* o2 = out + HBFD + ((size_t)h * B + b) * (F * D);
#pragma unroll
        for (int nt = 0; nt < 8; nt++) {
            int c = 8 * nt + L.qc;
            int r1 = f0 + L.qr, r2 = r1 + 8;
            *(float2*)(o2 + r1 * 64 + c) = make_float2(acc[nt][0], acc[nt][1]);
            *(float2*)(o2 + r2 * 64 + c) = make_float2(acc[nt][2], acc[nt][3]);
        }
    }

    // ================= K projection (V == K per reference) -> smem =========
    proj3(acc, sb, WKH, WKL, xfh, xfl, L);
#pragma unroll
    for (int nt = 0; nt < 8; nt++) {
        int c2 = (8 * nt + L.qc) * 2;
        int r1 = f0 + L.qr, r2 = r1 + 8;
        u32 hi, lo;
        split2(acc[nt][0], acc[nt][1], hi, lo);
        *(u32*)(sm + KH + r1 * SB64 + c2) = hi;
        *(u32*)(sm + KL + r1 * SB64 + c2) = lo;
        split2(acc[nt][2], acc[nt][3], hi, lo);
        *(u32*)(sm + KH + r2 * SB64 + c2) = hi;
        *(u32*)(sm + KL + r2 * SB64 + c2) = lo;
    }
    __syncthreads();   // K visible to all warps

    // ============ fused S -> sigmoid -> O, by 64-column g-halves ============
    float oc[8][4];
#pragma unroll
    for (int nt = 0; nt < 8; nt++)
#pragma unroll
        for (int j = 0; j < 4; j++) oc[nt][j] = 0.f;

#pragma unroll
    for (int hb = 0; hb < 2; hb++) {
        // ---- S half: rows f0..f0+15, cols g in [64*hb, 64*hb+64) ----
        // 2-term split (qh*kh + ql*kh): K-lo contributes ~1e-4 rel, dropped.
        float sacc[8][4];
#pragma unroll
        for (int nt = 0; nt < 8; nt++)
#pragma unroll
            for (int j = 0; j < 4; j++) sacc[nt][j] = 0.f;
#pragma unroll
        for (int ks = 0; ks < 4; ks++) {
            u32 ah0 = qfh[4 * ks], ah1 = qfh[4 * ks + 1], ah2 = qfh[4 * ks + 2], ah3 = qfh[4 * ks + 3];
            u32 al0 = qfl[4 * ks], al1 = qfl[4 * ks + 1], al2 = qfl[4 * ks + 2], al3 = qfl[4 * ks + 3];
#pragma unroll
            for (int n2 = 0; n2 < 4; n2++) {
                u32 aB = sb + (u32)((16 * (4 * hb + n2) + L.bn) * SB64 + 32 * ks + L.bk * 16);
                u32 bh0, bh1, bh2, bh3;
                ldsm4(bh0, bh1, bh2, bh3, aB + KH);
                mma16816(sacc[2 * n2],     ah0, ah1, ah2, ah3, bh0, bh1);
                mma16816(sacc[2 * n2 + 1], ah0, ah1, ah2, ah3, bh2, bh3);
                mma16816(sacc[2 * n2],     al0, al1, al2, al3, bh0, bh1);
                mma16816(sacc[2 * n2 + 1], al0, al1, al2, al3, bh2, bh3);
            }
        }

        // ---- sigmoid chunk (16 g) -> O k-step, fragments die immediately ----
#pragma unroll
        for (int ks2 = 0; ks2 < 4; ks2++) {
            u32 afh[4], afl[4];
#pragma unroll
            for (int half = 0; half < 2; half++) {
                int nt = 2 * ks2 + half;
                float a0 = 1.0f / (1.0f + __expf(-0.125f * sacc[nt][0]));
                float a1 = 1.0f / (1.0f + __expf(-0.125f * sacc[nt][1]));
                float a2 = 1.0f / (1.0f + __expf(-0.125f * sacc[nt][2]));
                float a3 = 1.0f / (1.0f + __expf(-0.125f * sacc[nt][3]));
                split2(a0, a1, afh[2 * half],     afl[2 * half]);
                split2(a2, a3, afh[2 * half + 1], afl[2 * half + 1]);
            }
#pragma unroll
            for (int n2 = 0; n2 < 4; n2++) {
                u32 aB = sb + (u32)((16 * (4 * hb + ks2) + L.tg) * SB64 + (16 * n2 + L.td) * 2);
                u32 bh0, bh1, bh2, bh3, bl0, bl1, bl2, bl3;
                ldsm4t(bh0, bh1, bh2, bh3, aB + KH);
                ldsm4t(bl0, bl1, bl2, bl3, aB + KL);
                mma16816(oc[2 * n2],     afh[0], afh[1], afh[2], afh[3], bh0, bh1);
                mma16816(oc[2 * n2 + 1], afh[0], afh[1], afh[2], afh[3], bh2, bh3);
                mma16816(oc[2 * n2],     afh[0], afh[1], afh[2], afh[3], bl0, bl1);
                mma16816(oc[2 * n2 + 1], afh[0], afh[1], afh[2], afh[3], bl2, bl3);
                mma16816(oc[2 * n2],     afl[0], afl[1], afl[2], afl[3], bh0, bh1);
                mma16816(oc[2 * n2 + 1], afl[0], afl[1], afl[2], afl[3], bh2, bh3);
            }
        }
    }

    // ---- LayerNorm rows + store out1 ----
    {
        float s1 = 0.f, q1 = 0.f, s2 = 0.f, q2 = 0.f;
#pragma unroll
        for (int nt = 0; nt < 8; nt++) {
            s1 += oc[nt][0] + oc[nt][1];
            q1 += oc[nt][0] * oc[nt][0] + oc[nt][1] * oc[nt][1];
            s2 += oc[nt][2] + oc[nt][3];
            q2 += oc[nt][2] * oc[nt][2] + oc[nt][3] * oc[nt][3];
        }
#pragma unroll
        for (int off = 1; off <= 2; off <<= 1) {
            s1 += __shfl_xor_sync(0xFFFFFFFFu, s1, off);
            q1 += __shfl_xor_sync(0xFFFFFFFFu, q1, off);
            s2 += __shfl_xor_sync(0xFFFFFFFFu, s2, off);
            q2 += __shfl_xor_sync(0xFFFFFFFFu, q2, off);
        }
        float mu1 = s1 * (1.0f / 64.0f);
        float v1 = q1 * (1.0f / 64.0f) - mu1 * mu1;
        float sc1 = rsqrtf(v1 + 1e-3f);
        float mu2 = s2 * (1.0f / 64.0f);
        float v2 = q2 * (1.0f / 64.0f) - mu2 * mu2;
        float sc2 = rsqrtf(v2 + 1e-3f);

        float* o1 = out + ((size_t)h * B + b) * (F * D);
        int r1 = f0 + L.qr, r2 = r1 + 8;
#pragma unroll
        for (int nt = 0; nt < 8; nt++) {
            int c = 8 * nt + L.qc;
            float g0 = gmS[c], g1 = gmS[c + 1];
            float b0 = gmS[64 + c], b1 = gmS[64 + c + 1];
            float2 v;
            v.x = (oc[nt][0] - mu1) * sc1 * g0 + b0;
            v.y = (oc[nt][1] - mu1) * sc1 * g1 + b1;
            *(float2*)(o1 + r1 * 64 + c) = v;
            v.x = (oc[nt][2] - mu2) * sc2 * g0 + b0;
            v.y = (oc[nt][3] - mu2) * sc2 * g1 + b1;
            *(float2*)(o1 + r2 * 64 + c) = v;
        }
    }
}

extern "C" void kernel_launch(void* const* d_in, const int* in_sizes, int n_in,
                              void* d_out, int out_size) {
    const float* x     = (const float*)d_in[0];
    const float* wq    = (const float*)d_in[1];
    const float* wk    = (const float*)d_in[2];
    const float* wr    = (const float*)d_in[3];
    const float* gamma = (const float*)d_in[4];
    const float* beta  = (const float*)d_in[5];
    float* out = (float*)d_out;

    int B = in_sizes[0] / (F * DIN);

    cudaFuncSetAttribute(mha_hmma_kernel,
                         cudaFuncAttributeMaxDynamicSharedMemorySize, SMEM_TOTAL);

    dim3 grid(H, B);
    mha_hmma_kernel<<<grid, 256, SMEM_TOTAL>>>(x, wq, wk, wr, gamma, beta, out, B);
}

// round 12
// speedup vs baseline: 1.7635x; 1.0396x over previous
#include <cuda_runtime.h>
#include <cstdint>

typedef unsigned int u32;
typedef unsigned long long u64;
#define DEVINL __device__ __forceinline__

constexpr int F = 128, DIN = 64, D = 64, H = 8;

// smem byte offsets; 64-col bf16 arrays use stride 144B (16B-aligned rows for ldsm)
constexpr u32 SB64 = 144;
// X stage aliased with K (X fragments are captured to regs before K is stored)
constexpr u32 KH = 0;               // X hi, later K hi   [128][64] (+pad)
constexpr u32 KL = 18432;           // X lo, later K lo
// W stored [i][d] (k-major rows): STS conflict-free, B-frags via ldsm4t
constexpr u32 WQH = 36864;                 // Wq hi only (2-term Q)
constexpr u32 WKH = 46080, WKL = 55296;    // Wk hi/lo
constexpr u32 WRH = 64512, WRL = 73728;    // Wr hi/lo
constexpr u32 GB = 82944;           // gamma[64] f32, beta[64] f32
constexpr u32 SMEM_TOTAL = 83456;

DEVINL u32 s2u(const void* p) {
    u32 a; asm("{ .reg .u64 t; cvta.to.shared.u64 t, %1; cvt.u32.u64 %0, t; }" : "=r"(a) : "l"(p));
    return a;
}
DEVINL void ldsm4(u32& r0, u32& r1, u32& r2, u32& r3, u32 a) {
    asm volatile("ldmatrix.sync.aligned.m8n8.x4.shared.b16 {%0,%1,%2,%3}, [%4];"
                 : "=r"(r0), "=r"(r1), "=r"(r2), "=r"(r3) : "r"(a));
}
DEVINL void ldsm4t(u32& r0, u32& r1, u32& r2, u32& r3, u32 a) {
    asm volatile("ldmatrix.sync.aligned.m8n8.x4.trans.shared.b16 {%0,%1,%2,%3}, [%4];"
                 : "=r"(r0), "=r"(r1), "=r"(r2), "=r"(r3) : "r"(a));
}
DEVINL void mma16816(float* c, u32 a0, u32 a1, u32 a2, u32 a3, u32 b0, u32 b1) {
    asm volatile("mma.sync.aligned.m16n8k16.row.col.f32.bf16.bf16.f32 "
                 "{%0,%1,%2,%3}, {%4,%5,%6,%7}, {%8,%9}, {%0,%1,%2,%3};"
                 : "+f"(c[0]), "+f"(c[1]), "+f"(c[2]), "+f"(c[3])
                 : "r"(a0), "r"(a1), "r"(a2), "r"(a3), "r"(b0), "r"(b1));
}
// pack two floats -> bf16x2 (x low half, y high half)
DEVINL u32 cvt2(float x, float y) {
    u32 r; asm("cvt.rn.bf16x2.f32 %0, %1, %2;" : "=r"(r) : "f"(y), "f"(x)); return r;
}
DEVINL void split2(float x, float y, u32& hi, u32& lo) {
    hi = cvt2(x, y);
    float rx = x - __uint_as_float(hi << 16);
    float ry = y - __uint_as_float(hi & 0xFFFF0000u);
    lo = cvt2(rx, ry);
}

struct Lane {
    int lr16, lh;   // A-ldsm addressing
    int bn, bk;     // B plain (K-as-[n][k]) addressing
    int tg, td;     // B trans ([k][n] storage) addressing
    int qr, qc;     // C fragment row/col
};

// 16x64x64 projection, A-fragments in registers, W stored [i][d] read via ldsm4t.
// THREE: include the xh*wl term (3-term split) or not (2-term).
template <bool THREE>
DEVINL void projT(float (*acc)[4], u32 sb, u32 WHb, u32 WLb,
                  const u32* xfh, const u32* xfl, const Lane& L) {
#pragma unroll
    for (int nt = 0; nt < 8; nt++)
#pragma unroll
        for (int j = 0; j < 4; j++) acc[nt][j] = 0.f;
#pragma unroll
    for (int ks = 0; ks < 4; ks++) {
        u32 ah0 = xfh[4 * ks], ah1 = xfh[4 * ks + 1], ah2 = xfh[4 * ks + 2], ah3 = xfh[4 * ks + 3];
        u32 al0 = xfl[4 * ks], al1 = xfl[4 * ks + 1], al2 = xfl[4 * ks + 2], al3 = xfl[4 * ks + 3];
#pragma unroll
        for (int n2 = 0; n2 < 4; n2++) {
            u32 aB = sb + (u32)((16 * ks + L.tg) * SB64 + (16 * n2 + L.td) * 2);
            u32 bh0, bh1, bh2, bh3;
            ldsm4t(bh0, bh1, bh2, bh3, aB + WHb);
            mma16816(acc[2 * n2],     ah0, ah1, ah2, ah3, bh0, bh1);
            mma16816(acc[2 * n2 + 1], ah0, ah1, ah2, ah3, bh2, bh3);
            mma16816(acc[2 * n2],     al0, al1, al2, al3, bh0, bh1);
            mma16816(acc[2 * n2 + 1], al0, al1, al2, al3, bh2, bh3);
            if (THREE) {
                u32 bl0, bl1, bl2, bl3;
                ldsm4t(bl0, bl1, bl2, bl3, aB + WLb);
                mma16816(acc[2 * n2],     ah0, ah1, ah2, ah3, bl0, bl1);
                mma16816(acc[2 * n2 + 1], ah0, ah1, ah2, ah3, bl2, bl3);
            }
        }
    }
}

__global__ void __launch_bounds__(256, 2)
mha_hmma_kernel(const float* __restrict__ x,
                const float* __restrict__ wq,
                const float* __restrict__ wk,
                const float* __restrict__ wr,
                const float* __restrict__ gamma,
                const float* __restrict__ beta,
                float* __restrict__ out, int B) {
    extern __shared__ __align__(1024) char sm[];
    const u32 sb = s2u(sm);
    const int tid = threadIdx.x;
    const int w = tid >> 5, lane = tid & 31;
    const int h = blockIdx.x, b = blockIdx.y;
    const int f0 = w * 16;
    const size_t HBFD = (size_t)H * B * F * D;

    Lane L;
    L.lr16 = lane & 15; L.lh = lane >> 4;
    L.bn = (lane & 7) + ((lane >> 4) & 1) * 8; L.bk = (lane >> 3) & 1;
    L.tg = (lane & 7) + ((lane >> 3) & 1) * 8; L.td = ((lane >> 4) & 1) * 8;
    L.qr = lane >> 2; L.qc = (lane & 3) * 2;

    float* const gmS = (float*)(sm + GB);        // gamma[0..63], beta[64..127]
    if (tid < 128) gmS[tid] = (tid < 64) ? gamma[tid] : beta[tid - 64];

    // ---- X[b] -> bf16 hi/lo [f][i] into the (future K) region ----
    {
        const float4* xg = (const float4*)(x + (size_t)b * F * DIN);
#pragma unroll
        for (int k = 0; k < 8; k++) {
            int idx4 = tid + 256 * k;
            int f = idx4 >> 4, i4 = (idx4 & 15) * 4;
            float4 v = xg[idx4];
            u32 h0, l0, h1, l1;
            split2(v.x, v.y, h0, l0);
            split2(v.z, v.w, h1, l1);
            u32 off = (u32)(f * SB64 + i4 * 2);
            *(uint2*)(sm + KH + off) = make_uint2(h0, h1);
            *(uint2*)(sm + KL + off) = make_uint2(l0, l1);
        }
    }

    // ---- W's upfront: [i][d] rows, conflict-free STS, coalesced LDG ----
    // warp-uniform row i per iteration; lanes span d -> contiguous 4B stores.
    auto loadW = [&](const float* __restrict__ wp, u32 WHb, u32 WLb, bool dolo) {
#pragma unroll
        for (int it = 0; it < 8; it++) {
            int i = 8 * it + w;
            int d2 = lane * 2;
            float2 v = *(const float2*)&wp[i * (H * D) + h * D + d2];
            u32 hi, lo;
            split2(v.x, v.y, hi, lo);
            *(u32*)(sm + WHb + i * SB64 + d2 * 2) = hi;
            if (dolo) *(u32*)(sm + WLb + i * SB64 + d2 * 2) = lo;
        }
    };
    loadW(wq, WQH, 0, false);          // Q is 2-term: hi only
    loadW(wk, WKH, WKL, true);
    loadW(wr, WRH, WRL, true);
    __syncthreads();

    // ---- capture X A-fragments to registers (once, reused by 3 projections) ----
    u32 xfh[16], xfl[16];
#pragma unroll
    for (int ks = 0; ks < 4; ks++) {
        u32 aA = sb + (u32)((f0 + L.lr16) * SB64 + 32 * ks + L.lh * 16);
        ldsm4(xfh[4 * ks], xfh[4 * ks + 1], xfh[4 * ks + 2], xfh[4 * ks + 3], aA + KH);
        ldsm4(xfl[4 * ks], xfl[4 * ks + 1], xfl[4 * ks + 2], xfl[4 * ks + 3], aA + KL);
    }
    __syncthreads();   // all warps captured X; K region may now be overwritten

    float acc[8][4];

    // ================= Q projection (2-term) -> qf registers =================
    projT<false>(acc, sb, WQH, 0, xfh, xfl, L);
    u32 qfh[16], qfl[16];
#pragma unroll
    for (int ks = 0; ks < 4; ks++) {
        split2(acc[2 * ks][0],     acc[2 * ks][1],     qfh[4 * ks + 0], qfl[4 * ks + 0]);
        split2(acc[2 * ks][2],     acc[2 * ks][3],     qfh[4 * ks + 1], qfl[4 * ks + 1]);
        split2(acc[2 * ks + 1][0], acc[2 * ks + 1][1], qfh[4 * ks + 2], qfl[4 * ks + 2]);
        split2(acc[2 * ks + 1][2], acc[2 * ks + 1][3], qfh[4 * ks + 3], qfl[4 * ks + 3]);
    }

    // ================= R projection (3-term) -> direct STG =================
    projT<true>(acc, sb, WRH, WRL, xfh, xfl, L);
    {
        float* o2 = out + HBFD + ((size_t)h * B + b) * (F * D);
#pragma unroll
        for (int nt = 0; nt < 8; nt++) {
            int c = 8 * nt + L.qc;
            int r1 = f0 + L.qr, r2 = r1 + 8;
            *(float2*)(o2 + r1 * 64 + c) = make_float2(acc[nt][0], acc[nt][1]);
            *(float2*)(o2 + r2 * 64 + c) = make_float2(acc[nt][2], acc[nt][3]);
        }
    }

    // ============ K projection (3-term; V == K per reference) -> smem =======
    projT<true>(acc, sb, WKH, WKL, xfh, xfl, L);
#pragma unroll
    for (int nt = 0; nt < 8; nt++) {
        int c2 = (8 * nt + L.qc) * 2;
        int r1 = f0 + L.qr, r2 = r1 + 8;
        u32 hi, lo;
        split2(acc[nt][0], acc[nt][1], hi, lo);
        *(u32*)(sm + KH + r1 * SB64 + c2) = hi;
        *(u32*)(sm + KL + r1 * SB64 + c2) = lo;
        split2(acc[nt][2], acc[nt][3], hi, lo);
        *(u32*)(sm + KH + r2 * SB64 + c2) = hi;
        *(u32*)(sm + KL + r2 * SB64 + c2) = lo;
    }
    __syncthreads();   // K visible to all warps

    // ============ fused S -> sigmoid -> O, by 64-column g-halves ============
    float oc[8][4];
#pragma unroll
    for (int nt = 0; nt < 8; nt++)
#pragma unroll
        for (int j = 0; j < 4; j++) oc[nt][j] = 0.f;

#pragma unroll
    for (int hb = 0; hb < 2; hb++) {
        // ---- S half: rows f0..f0+15, cols g in [64*hb, 64*hb+64) ----
        // 2-term split (qh*kh + ql*kh)
        float sacc[8][4];
#pragma unroll
        for (int nt = 0; nt < 8; nt++)
#pragma unroll
            for (int j = 0; j < 4; j++) sacc[nt][j] = 0.f;
#pragma unroll
        for (int ks = 0; ks < 4; ks++) {
            u32 ah0 = qfh[4 * ks], ah1 = qfh[4 * ks + 1], ah2 = qfh[4 * ks + 2], ah3 = qfh[4 * ks + 3];
            u32 al0 = qfl[4 * ks], al1 = qfl[4 * ks + 1], al2 = qfl[4 * ks + 2], al3 = qfl[4 * ks + 3];
#pragma unroll
            for (int n2 = 0; n2 < 4; n2++) {
                u32 aB = sb + (u32)((16 * (4 * hb + n2) + L.bn) * SB64 + 32 * ks + L.bk * 16);
                u32 bh0, bh1, bh2, bh3;
                ldsm4(bh0, bh1, bh2, bh3, aB + KH);
                mma16816(sacc[2 * n2],     ah0, ah1, ah2, ah3, bh0, bh1);
                mma16816(sacc[2 * n2 + 1], ah0, ah1, ah2, ah3, bh2, bh3);
                mma16816(sacc[2 * n2],     al0, al1, al2, al3, bh0, bh1);
                mma16816(sacc[2 * n2 + 1], al0, al1, al2, al3, bh2, bh3);
            }
        }

        // ---- sigmoid chunk (16 g) -> O k-step, fragments die immediately ----
#pragma unroll
        for (int ks2 = 0; ks2 < 4; ks2++) {
            u32 afh[4], afl[4];
#pragma unroll
            for (int half = 0; half < 2; half++) {
                int nt = 2 * ks2 + half;
                float a0 = 1.0f / (1.0f + __expf(-0.125f * sacc[nt][0]));
                float a1 = 1.0f / (1.0f + __expf(-0.125f * sacc[nt][1]));
                float a2 = 1.0f / (1.0f + __expf(-0.125f * sacc[nt][2]));
                float a3 = 1.0f / (1.0f + __expf(-0.125f * sacc[nt][3]));
                split2(a0, a1, afh[2 * half],     afl[2 * half]);
                split2(a2, a3, afh[2 * half + 1], afl[2 * half + 1]);
            }
#pragma unroll
            for (int n2 = 0; n2 < 4; n2++) {
                u32 aB = sb + (u32)((16 * (4 * hb + ks2) + L.tg) * SB64 + (16 * n2 + L.td) * 2);
                u32 bh0, bh1, bh2, bh3, bl0, bl1, bl2, bl3;
                ldsm4t(bh0, bh1, bh2, bh3, aB + KH);
                ldsm4t(bl0, bl1, bl2, bl3, aB + KL);
                mma16816(oc[2 * n2],     afh[0], afh[1], afh[2], afh[3], bh0, bh1);
                mma16816(oc[2 * n2 + 1], afh[0], afh[1], afh[2], afh[3], bh2, bh3);
                mma16816(oc[2 * n2],     afh[0], afh[1], afh[2], afh[3], bl0, bl1);
                mma16816(oc[2 * n2 + 1], afh[0], afh[1], afh[2], afh[3], bl2, bl3);
                mma16816(oc[2 * n2],     afl[0], afl[1], afl[2], afl[3], bh0, bh1);
                mma16816(oc[2 * n2 + 1], afl[0], afl[1], afl[2], afl[3], bh2, bh3);
            }
        }
    }

    // ---- LayerNorm rows + store out1 ----
    {
        float s1 = 0.f, q1 = 0.f, s2 = 0.f, q2 = 0.f;
#pragma unroll
        for (int nt = 0; nt < 8; nt++) {
            s1 += oc[nt][0] + oc[nt][1];
            q1 += oc[nt][0] * oc[nt][0] + oc[nt][1] * oc[nt][1];
            s2 += oc[nt][2] + oc[nt][3];
            q2 += oc[nt][2] * oc[nt][2] + oc[nt][3] * oc[nt][3];
        }
#pragma unroll
        for (int off = 1; off <= 2; off <<= 1) {
            s1 += __shfl_xor_sync(0xFFFFFFFFu, s1, off);
            q1 += __shfl_xor_sync(0xFFFFFFFFu, q1, off);
            s2 += __shfl_xor_sync(0xFFFFFFFFu, s2, off);
            q2 += __shfl_xor_sync(0xFFFFFFFFu, q2, off);
        }
        float mu1 = s1 * (1.0f / 64.0f);
        float v1 = q1 * (1.0f / 64.0f) - mu1 * mu1;
        float sc1 = rsqrtf(v1 + 1e-3f);
        float mu2 = s2 * (1.0f / 64.0f);
        float v2 = q2 * (1.0f / 64.0f) - mu2 * mu2;
        float sc2 = rsqrtf(v2 + 1e-3f);

        float* o1 = out + ((size_t)h * B + b) * (F * D);
        int r1 = f0 + L.qr, r2 = r1 + 8;
#pragma unroll
        for (int nt = 0; nt < 8; nt++) {
            int c = 8 * nt + L.qc;
            float g0 = gmS[c], g1 = gmS[c + 1];
            float b0 = gmS[64 + c], b1 = gmS[64 + c + 1];
            float2 v;
            v.x = (oc[nt][0] - mu1) * sc1 * g0 + b0;
            v.y = (oc[nt][1] - mu1) * sc1 * g1 + b1;
            *(float2*)(o1 + r1 * 64 + c) = v;
            v.x = (oc[nt][2] - mu2) * sc2 * g0 + b0;
            v.y = (oc[nt][3] - mu2) * sc2 * g1 + b1;
            *(float2*)(o1 + r2 * 64 + c) = v;
        }
    }
}

extern "C" void kernel_launch(void* const* d_in, const int* in_sizes, int n_in,
                              void* d_out, int out_size) {
    const float* x     = (const float*)d_in[0];
    const float* wq    = (const float*)d_in[1];
    const float* wk    = (const float*)d_in[2];
    const float* wr    = (const float*)d_in[3];
    const float* gamma = (const float*)d_in[4];
    const float* beta  = (const float*)d_in[5];
    float* out = (float*)d_out;

    int B = in_sizes[0] / (F * DIN);

    cudaFuncSetAttribute(mha_hmma_kernel,
                         cudaFuncAttributeMaxDynamicSharedMemorySize, SMEM_TOTAL);

    dim3 grid(H, B);
    mha_hmma_kernel<<<grid, 256, SMEM_TOTAL>>>(x, wq, wk, wr, gamma, beta, out, B);
}

// round 13
// speedup vs baseline: 2.0025x; 1.1355x over previous
#include <cuda_runtime.h>
#include <cuda_fp16.h>
#include <cstdint>

typedef unsigned int u32;
typedef unsigned long long u64;
#define DEVINL __device__ __forceinline__

constexpr int F = 128, DIN = 64, D = 64, H = 8;

// smem byte offsets; 64-col 16-bit arrays use stride 144B (16B-aligned rows for ldsm)
constexpr u32 SB64 = 144;
// X-hi stage aliased with K (X fragments captured to regs before K is stored)
constexpr u32 KH = 0;               // X hi (bf16), later K (fp16)  [128][64]
constexpr u32 KL = 18432;           // X lo (bf16) staging only
// W stored [i][d] (k-major rows): STS conflict-free, B-frags via ldsm4t
constexpr u32 WQH = 36864;                 // Wq hi only (2-term Q)
constexpr u32 WKH = 46080, WKL = 55296;    // Wk hi/lo
constexpr u32 WRH = 64512, WRL = 73728;    // Wr hi/lo
constexpr u32 GB = 82944;           // gamma[64] f32, beta[64] f32
constexpr u32 SMEM_TOTAL = 83456;

DEVINL u32 s2u(const void* p) {
    u32 a; asm("{ .reg .u64 t; cvta.to.shared.u64 t, %1; cvt.u32.u64 %0, t; }" : "=r"(a) : "l"(p));
    return a;
}
DEVINL void ldsm4(u32& r0, u32& r1, u32& r2, u32& r3, u32 a) {
    asm volatile("ldmatrix.sync.aligned.m8n8.x4.shared.b16 {%0,%1,%2,%3}, [%4];"
                 : "=r"(r0), "=r"(r1), "=r"(r2), "=r"(r3) : "r"(a));
}
DEVINL void ldsm4t(u32& r0, u32& r1, u32& r2, u32& r3, u32 a) {
    asm volatile("ldmatrix.sync.aligned.m8n8.x4.trans.shared.b16 {%0,%1,%2,%3}, [%4];"
                 : "=r"(r0), "=r"(r1), "=r"(r2), "=r"(r3) : "r"(a));
}
// bf16 mma
DEVINL void mma16816(float* c, u32 a0, u32 a1, u32 a2, u32 a3, u32 b0, u32 b1) {
    asm volatile("mma.sync.aligned.m16n8k16.row.col.f32.bf16.bf16.f32 "
                 "{%0,%1,%2,%3}, {%4,%5,%6,%7}, {%8,%9}, {%0,%1,%2,%3};"
                 : "+f"(c[0]), "+f"(c[1]), "+f"(c[2]), "+f"(c[3])
                 : "r"(a0), "r"(a1), "r"(a2), "r"(a3), "r"(b0), "r"(b1));
}
// fp16 mma
DEVINL void mma16816h(float* c, u32 a0, u32 a1, u32 a2, u32 a3, u32 b0, u32 b1) {
    asm volatile("mma.sync.aligned.m16n8k16.row.col.f32.f16.f16.f32 "
                 "{%0,%1,%2,%3}, {%4,%5,%6,%7}, {%8,%9}, {%0,%1,%2,%3};"
                 : "+f"(c[0]), "+f"(c[1]), "+f"(c[2]), "+f"(c[3])
                 : "r"(a0), "r"(a1), "r"(a2), "r"(a3), "r"(b0), "r"(b1));
}
// pack two floats -> bf16x2 (x low half, y high half)
DEVINL u32 cvt2(float x, float y) {
    u32 r; asm("cvt.rn.bf16x2.f32 %0, %1, %2;" : "=r"(r) : "f"(y), "f"(x)); return r;
}
DEVINL void split2(float x, float y, u32& hi, u32& lo) {
    hi = cvt2(x, y);
    float rx = x - __uint_as_float(hi << 16);
    float ry = y - __uint_as_float(hi & 0xFFFF0000u);
    lo = cvt2(rx, ry);
}
// pack two floats -> fp16x2 (x low half, y high half)
DEVINL u32 cvt2h(float x, float y) {
    u32 r; asm("cvt.rn.f16x2.f32 %0, %1, %2;" : "=r"(r) : "f"(y), "f"(x)); return r;
}
// fp16 split: hi + fp16 residual (A exact to ~2^-23)
DEVINL void split2h(float x, float y, u32& hi, u32& lo) {
    hi = cvt2h(x, y);
    __half2 h = *reinterpret_cast<__half2*>(&hi);
    float2 f = __half22float2(h);
    lo = cvt2h(x - f.x, y - f.y);
}

struct Lane {
    int lr16, lh;   // A-ldsm addressing
    int bn, bk;     // B plain ([n][k]) addressing
    int tg, td;     // B trans ([k][n] storage) addressing
    int qr, qc;     // C fragment row/col
};

// 16x64x64 projection (bf16), A-fragments in registers, W [i][d] via ldsm4t.
template <bool THREE>
DEVINL void projT(float (*acc)[4], u32 sb, u32 WHb, u32 WLb,
                  const u32* xfh, const u32* xfl, const Lane& L) {
#pragma unroll
    for (int nt = 0; nt < 8; nt++)
#pragma unroll
        for (int j = 0; j < 4; j++) acc[nt][j] = 0.f;
#pragma unroll
    for (int ks = 0; ks < 4; ks++) {
        u32 ah0 = xfh[4 * ks], ah1 = xfh[4 * ks + 1], ah2 = xfh[4 * ks + 2], ah3 = xfh[4 * ks + 3];
        u32 al0 = xfl[4 * ks], al1 = xfl[4 * ks + 1], al2 = xfl[4 * ks + 2], al3 = xfl[4 * ks + 3];
#pragma unroll
        for (int n2 = 0; n2 < 4; n2++) {
            u32 aB = sb + (u32)((16 * ks + L.tg) * SB64 + (16 * n2 + L.td) * 2);
            u32 bh0, bh1, bh2, bh3;
            ldsm4t(bh0, bh1, bh2, bh3, aB + WHb);
            mma16816(acc[2 * n2],     ah0, ah1, ah2, ah3, bh0, bh1);
            mma16816(acc[2 * n2 + 1], ah0, ah1, ah2, ah3, bh2, bh3);
            mma16816(acc[2 * n2],     al0, al1, al2, al3, bh0, bh1);
            mma16816(acc[2 * n2 + 1], al0, al1, al2, al3, bh2, bh3);
            if (THREE) {
                u32 bl0, bl1, bl2, bl3;
                ldsm4t(bl0, bl1, bl2, bl3, aB + WLb);
                mma16816(acc[2 * n2],     ah0, ah1, ah2, ah3, bl0, bl1);
                mma16816(acc[2 * n2 + 1], ah0, ah1, ah2, ah3, bl2, bl3);
            }
        }
    }
}

__global__ void __launch_bounds__(256, 2)
mha_hmma_kernel(const float* __restrict__ x,
                const float* __restrict__ wq,
                const float* __restrict__ wk,
                const float* __restrict__ wr,
                const float* __restrict__ gamma,
                const float* __restrict__ beta,
                float* __restrict__ out, int B) {
    extern __shared__ __align__(1024) char sm[];
    const u32 sb = s2u(sm);
    const int tid = threadIdx.x;
    const int w = tid >> 5, lane = tid & 31;
    const int h = blockIdx.x, b = blockIdx.y;
    const int f0 = w * 16;
    const size_t HBFD = (size_t)H * B * F * D;

    Lane L;
    L.lr16 = lane & 15; L.lh = lane >> 4;
    L.bn = (lane & 7) + ((lane >> 4) & 1) * 8; L.bk = (lane >> 3) & 1;
    L.tg = (lane & 7) + ((lane >> 3) & 1) * 8; L.td = ((lane >> 4) & 1) * 8;
    L.qr = lane >> 2; L.qc = (lane & 3) * 2;

    float* const gmS = (float*)(sm + GB);        // gamma[0..63], beta[64..127]
    if (tid < 128) gmS[tid] = (tid < 64) ? gamma[tid] : beta[tid - 64];

    // ---- X[b] -> bf16 hi/lo [f][i] (hi into the future-K region) ----
    {
        const float4* xg = (const float4*)(x + (size_t)b * F * DIN);
#pragma unroll
        for (int k = 0; k < 8; k++) {
            int idx4 = tid + 256 * k;
            int f = idx4 >> 4, i4 = (idx4 & 15) * 4;
            float4 v = xg[idx4];
            u32 h0, l0, h1, l1;
            split2(v.x, v.y, h0, l0);
            split2(v.z, v.w, h1, l1);
            u32 off = (u32)(f * SB64 + i4 * 2);
            *(uint2*)(sm + KH + off) = make_uint2(h0, h1);
            *(uint2*)(sm + KL + off) = make_uint2(l0, l1);
        }
    }

    // ---- W's upfront: [i][d] rows, conflict-free STS, coalesced LDG ----
    auto loadW = [&](const float* __restrict__ wp, u32 WHb, u32 WLb, bool dolo) {
#pragma unroll
        for (int it = 0; it < 8; it++) {
            int i = 8 * it + w;
            int d2 = lane * 2;
            float2 v = *(const float2*)&wp[i * (H * D) + h * D + d2];
            u32 hi, lo;
            split2(v.x, v.y, hi, lo);
            *(u32*)(sm + WHb + i * SB64 + d2 * 2) = hi;
            if (dolo) *(u32*)(sm + WLb + i * SB64 + d2 * 2) = lo;
        }
    };
    loadW(wq, WQH, 0, false);          // Q is 2-term: hi only
    loadW(wk, WKH, WKL, true);
    loadW(wr, WRH, WRL, true);
    __syncthreads();

    // ---- capture X A-fragments to registers (once, reused by 3 projections) ----
    u32 xfh[16], xfl[16];
#pragma unroll
    for (int ks = 0; ks < 4; ks++) {
        u32 aA = sb + (u32)((f0 + L.lr16) * SB64 + 32 * ks + L.lh * 16);
        ldsm4(xfh[4 * ks], xfh[4 * ks + 1], xfh[4 * ks + 2], xfh[4 * ks + 3], aA + KH);
        ldsm4(xfl[4 * ks], xfl[4 * ks + 1], xfl[4 * ks + 2], xfl[4 * ks + 3], aA + KL);
    }
    __syncthreads();   // all warps captured X; KH region may now be overwritten

    float acc[8][4];

    // ================= Q projection (2-term bf16) -> fp16 qf registers =======
    projT<false>(acc, sb, WQH, 0, xfh, xfl, L);
    u32 qf[16];
#pragma unroll
    for (int ks = 0; ks < 4; ks++) {
        qf[4 * ks + 0] = cvt2h(acc[2 * ks][0],     acc[2 * ks][1]);
        qf[4 * ks + 1] = cvt2h(acc[2 * ks][2],     acc[2 * ks][3]);
        qf[4 * ks + 2] = cvt2h(acc[2 * ks + 1][0], acc[2 * ks + 1][1]);
        qf[4 * ks + 3] = cvt2h(acc[2 * ks + 1][2], acc[2 * ks + 1][3]);
    }

    // ================= R projection (3-term bf16) -> direct STG =============
    projT<true>(acc, sb, WRH, WRL, xfh, xfl, L);
    {
        float* o2 = out + HBFD + ((size_t)h * B + b) * (F * D);
#pragma unroll
        for (int nt = 0; nt < 8; nt++) {
            int c = 8 * nt + L.qc;
            int r1 = f0 + L.qr, r2 = r1 + 8;
            *(float2*)(o2 + r1 * 64 + c) = make_float2(acc[nt][0], acc[nt][1]);
            *(float2*)(o2 + r2 * 64 + c) = make_float2(acc[nt][2], acc[nt][3]);
        }
    }

    // ====== K projection (3-term bf16; V == K per reference) -> fp16 smem ====
    projT<true>(acc, sb, WKH, WKL, xfh, xfl, L);
#pragma unroll
    for (int nt = 0; nt < 8; nt++) {
        int c2 = (8 * nt + L.qc) * 2;
        int r1 = f0 + L.qr, r2 = r1 + 8;
        *(u32*)(sm + KH + r1 * SB64 + c2) = cvt2h(acc[nt][0], acc[nt][1]);
        *(u32*)(sm + KH + r2 * SB64 + c2) = cvt2h(acc[nt][2], acc[nt][3]);
    }
    __syncthreads();   // K (fp16) visible to all warps

    // ============ fused S -> sigmoid -> O, by 64-column g-halves ============
    float oc[8][4];
#pragma unroll
    for (int nt = 0; nt < 8; nt++)
#pragma unroll
        for (int j = 0; j < 4; j++) oc[nt][j] = 0.f;

#pragma unroll
    for (int hb = 0; hb < 2; hb++) {
        // ---- S half: rows f0..f0+15, cols g in [64*hb, 64*hb+64), fp16 1-term
        float sacc[8][4];
#pragma unroll
        for (int nt = 0; nt < 8; nt++)
#pragma unroll
            for (int j = 0; j < 4; j++) sacc[nt][j] = 0.f;
#pragma unroll
        for (int ks = 0; ks < 4; ks++) {
            u32 a0 = qf[4 * ks], a1 = qf[4 * ks + 1], a2 = qf[4 * ks + 2], a3 = qf[4 * ks + 3];
#pragma unroll
            for (int n2 = 0; n2 < 4; n2++) {
                u32 aB = sb + (u32)((16 * (4 * hb + n2) + L.bn) * SB64 + 32 * ks + L.bk * 16);
                u32 bh0, bh1, bh2, bh3;
                ldsm4(bh0, bh1, bh2, bh3, aB + KH);
                mma16816h(sacc[2 * n2],     a0, a1, a2, a3, bh0, bh1);
                mma16816h(sacc[2 * n2 + 1], a0, a1, a2, a3, bh2, bh3);
            }
        }

        // ---- sigmoid chunk (16 g) -> O k-step (fp16 2-term A, 1-term K) ----
#pragma unroll
        for (int ks2 = 0; ks2 < 4; ks2++) {
            u32 afh[4], afl[4];
#pragma unroll
            for (int half = 0; half < 2; half++) {
                int nt = 2 * ks2 + half;
                float a0 = 1.0f / (1.0f + __expf(-0.125f * sacc[nt][0]));
                float a1 = 1.0f / (1.0f + __expf(-0.125f * sacc[nt][1]));
                float a2 = 1.0f / (1.0f + __expf(-0.125f * sacc[nt][2]));
                float a3 = 1.0f / (1.0f + __expf(-0.125f * sacc[nt][3]));
                split2h(a0, a1, afh[2 * half],     afl[2 * half]);
                split2h(a2, a3, afh[2 * half + 1], afl[2 * half + 1]);
            }
#pragma unroll
            for (int n2 = 0; n2 < 4; n2++) {
                u32 aB = sb + (u32)((16 * (4 * hb + ks2) + L.tg) * SB64 + (16 * n2 + L.td) * 2);
                u32 bh0, bh1, bh2, bh3;
                ldsm4t(bh0, bh1, bh2, bh3, aB + KH);
                mma16816h(oc[2 * n2],     afh[0], afh[1], afh[2], afh[3], bh0, bh1);
                mma16816h(oc[2 * n2 + 1], afh[0], afh[1], afh[2], afh[3], bh2, bh3);
                mma16816h(oc[2 * n2],     afl[0], afl[1], afl[2], afl[3], bh0, bh1);
                mma16816h(oc[2 * n2 + 1], afl[0], afl[1], afl[2], afl[3], bh2, bh3);
            }
        }
    }

    // ---- LayerNorm rows + store out1 ----
    {
        float s1 = 0.f, q1 = 0.f, s2 = 0.f, q2 = 0.f;
#pragma unroll
        for (int nt = 0; nt < 8; nt++) {
            s1 += oc[nt][0] + oc[nt][1];
            q1 += oc[nt][0] * oc[nt][0] + oc[nt][1] * oc[nt][1];
            s2 += oc[nt][2] + oc[nt][3];
            q2 += oc[nt][2] * oc[nt][2] + oc[nt][3] * oc[nt][3];
        }
#pragma unroll
        for (int off = 1; off <= 2; off <<= 1) {
            s1 += __shfl_xor_sync(0xFFFFFFFFu, s1, off);
            q1 += __shfl_xor_sync(0xFFFFFFFFu, q1, off);
            s2 += __shfl_xor_sync(0xFFFFFFFFu, s2, off);
            q2 += __shfl_xor_sync(0xFFFFFFFFu, q2, off);
        }
        float mu1 = s1 * (1.0f / 64.0f);
        float v1 = q1 * (1.0f / 64.0f) - mu1 * mu1;
        float sc1 = rsqrtf(v1 + 1e-3f);
        float mu2 = s2 * (1.0f / 64.0f);
        float v2 = q2 * (1.0f / 64.0f) - mu2 * mu2;
        float sc2 = rsqrtf(v2 + 1e-3f);

        float* o1 = out + ((size_t)h * B + b) * (F * D);
        int r1 = f0 + L.qr, r2 = r1 + 8;
#pragma unroll
        for (int nt = 0; nt < 8; nt++) {
            int c = 8 * nt + L.qc;
            float g0 = gmS[c], g1 = gmS[c + 1];
            float b0 = gmS[64 + c], b1 = gmS[64 + c + 1];
            float2 v;
            v.x = (oc[nt][0] - mu1) * sc1 * g0 + b0;
            v.y = (oc[nt][1] - mu1) * sc1 * g1 + b1;
            *(float2*)(o1 + r1 * 64 + c) = v;
            v.x = (oc[nt][2] - mu2) * sc2 * g0 + b0;
            v.y = (oc[nt][3] - mu2) * sc2 * g1 + b1;
            *(float2*)(o1 + r2 * 64 + c) = v;
        }
    }
}

extern "C" void kernel_launch(void* const* d_in, const int* in_sizes, int n_in,
                              void* d_out, int out_size) {
    const float* x     = (const float*)d_in[0];
    const float* wq    = (const float*)d_in[1];
    const float* wk    = (const float*)d_in[2];
    const float* wr    = (const float*)d_in[3];
    const float* gamma = (const float*)d_in[4];
    const float* beta  = (const float*)d_in[5];
    float* out = (float*)d_out;

    int B = in_sizes[0] / (F * DIN);

    cudaFuncSetAttribute(mha_hmma_kernel,
                         cudaFuncAttributeMaxDynamicSharedMemorySize, SMEM_TOTAL);

    dim3 grid(H, B);
    mha_hmma_kernel<<<grid, 256, SMEM_TOTAL>>>(x, wq, wk, wr, gamma, beta, out, B);
}

// round 14
// speedup vs baseline: 2.4349x; 1.2159x over previous
#include <cuda_runtime.h>
#include <cuda_fp16.h>
#include <cstdint>

typedef unsigned int u32;
typedef unsigned long long u64;
#define DEVINL __device__ __forceinline__

constexpr int F = 128, DIN = 64, D = 64, H = 8;

// Pre-converted fp16 weights: [p][h][i][d], p in {q,k,r}
__device__ __half2 g_wf[3 * H * DIN * D / 2];

// smem byte offsets; 64-col 16-bit arrays use stride 144B (16B-aligned rows for ldsm)
constexpr u32 SB64 = 144;
// X-hi stage aliased with K (X fragments captured to regs before K is stored)
constexpr u32 KH = 0;               // X hi (fp16), later K (fp16)  [128][64]
constexpr u32 KL = 18432;           // X lo (fp16) staging only
// W stored [i][d] (k-major rows), single fp16 buffer each
constexpr u32 WQ = 36864;
constexpr u32 WK = 46080;
constexpr u32 WR = 55296;
constexpr u32 GB = 64512;           // gamma[64] f32, beta[64] f32
constexpr u32 SMEM_TOTAL = 65024;

DEVINL u32 s2u(const void* p) {
    u32 a; asm("{ .reg .u64 t; cvta.to.shared.u64 t, %1; cvt.u32.u64 %0, t; }" : "=r"(a) : "l"(p));
    return a;
}
DEVINL void ldsm4(u32& r0, u32& r1, u32& r2, u32& r3, u32 a) {
    asm volatile("ldmatrix.sync.aligned.m8n8.x4.shared.b16 {%0,%1,%2,%3}, [%4];"
                 : "=r"(r0), "=r"(r1), "=r"(r2), "=r"(r3) : "r"(a));
}
DEVINL void ldsm4t(u32& r0, u32& r1, u32& r2, u32& r3, u32 a) {
    asm volatile("ldmatrix.sync.aligned.m8n8.x4.trans.shared.b16 {%0,%1,%2,%3}, [%4];"
                 : "=r"(r0), "=r"(r1), "=r"(r2), "=r"(r3) : "r"(a));
}
// fp16 mma
DEVINL void mma16816h(float* c, u32 a0, u32 a1, u32 a2, u32 a3, u32 b0, u32 b1) {
    asm volatile("mma.sync.aligned.m16n8k16.row.col.f32.f16.f16.f32 "
                 "{%0,%1,%2,%3}, {%4,%5,%6,%7}, {%8,%9}, {%0,%1,%2,%3};"
                 : "+f"(c[0]), "+f"(c[1]), "+f"(c[2]), "+f"(c[3])
                 : "r"(a0), "r"(a1), "r"(a2), "r"(a3), "r"(b0), "r"(b1));
}
// pack two floats -> fp16x2 (x low half, y high half)
DEVINL u32 cvt2h(float x, float y) {
    u32 r; asm("cvt.rn.f16x2.f32 %0, %1, %2;" : "=r"(r) : "f"(y), "f"(x)); return r;
}
// fp16 split: hi + fp16 residual (captures x to ~2^-22)
DEVINL void split2h(float x, float y, u32& hi, u32& lo) {
    hi = cvt2h(x, y);
    __half2 h = *reinterpret_cast<__half2*>(&hi);
    float2 f = __half22float2(h);
    lo = cvt2h(x - f.x, y - f.y);
}

struct Lane {
    int lr16, lh;   // A-ldsm addressing
    int bn, bk;     // B plain ([n][k]) addressing
    int tg, td;     // B trans ([k][n] storage) addressing
    int qr, qc;     // C fragment row/col
};

// 16x64x64 projection, fp16: 2-term X (hi+lo regs) x single-W, W [i][d] via ldsm4t.
DEVINL void projH(float (*acc)[4], u32 sb, u32 WB,
                  const u32* xfh, const u32* xfl, const Lane& L) {
#pragma unroll
    for (int nt = 0; nt < 8; nt++)
#pragma unroll
        for (int j = 0; j < 4; j++) acc[nt][j] = 0.f;
#pragma unroll
    for (int ks = 0; ks < 4; ks++) {
        u32 ah0 = xfh[4 * ks], ah1 = xfh[4 * ks + 1], ah2 = xfh[4 * ks + 2], ah3 = xfh[4 * ks + 3];
        u32 al0 = xfl[4 * ks], al1 = xfl[4 * ks + 1], al2 = xfl[4 * ks + 2], al3 = xfl[4 * ks + 3];
#pragma unroll
        for (int n2 = 0; n2 < 4; n2++) {
            u32 aB = sb + (u32)((16 * ks + L.tg) * SB64 + (16 * n2 + L.td) * 2);
            u32 b0, b1, b2, b3;
            ldsm4t(b0, b1, b2, b3, aB + WB);
            mma16816h(acc[2 * n2],     ah0, ah1, ah2, ah3, b0, b1);
            mma16816h(acc[2 * n2 + 1], ah0, ah1, ah2, ah3, b2, b3);
            mma16816h(acc[2 * n2],     al0, al1, al2, al3, b0, b1);
            mma16816h(acc[2 * n2 + 1], al0, al1, al2, al3, b2, b3);
        }
    }
}

// ---- weight pre-conversion kernel: f32 [i][h][d] -> fp16 [p][h][i][d] ----
__global__ void convw_kernel(const float* __restrict__ wq,
                             const float* __restrict__ wk,
                             const float* __restrict__ wr) {
    int idx = blockIdx.x * 256 + threadIdx.x;        // over 3*16384 half2
    constexpr int PER_M = H * DIN * D / 2;           // 16384
    int p = idx / PER_M;
    int r = idx % PER_M;
    int hh = r / (DIN * D / 2);
    int rr = r % (DIN * D / 2);
    int i = rr / (D / 2);
    int d2 = (rr % (D / 2)) * 2;
    const float* src = (p == 0) ? wq : (p == 1) ? wk : wr;
    float2 v = *(const float2*)&src[i * (H * D) + hh * D + d2];
    g_wf[idx] = __floats2half2_rn(v.x, v.y);
}

__global__ void __launch_bounds__(256, 2)
mha_hmma_kernel(const float* __restrict__ x,
                const float* __restrict__ gamma,
                const float* __restrict__ beta,
                float* __restrict__ out, int B) {
    extern __shared__ __align__(1024) char sm[];
    const u32 sb = s2u(sm);
    const int tid = threadIdx.x;
    const int w = tid >> 5, lane = tid & 31;
    const int h = blockIdx.x, b = blockIdx.y;
    const int f0 = w * 16;
    const size_t HBFD = (size_t)H * B * F * D;

    Lane L;
    L.lr16 = lane & 15; L.lh = lane >> 4;
    L.bn = (lane & 7) + ((lane >> 4) & 1) * 8; L.bk = (lane >> 3) & 1;
    L.tg = (lane & 7) + ((lane >> 3) & 1) * 8; L.td = ((lane >> 4) & 1) * 8;
    L.qr = lane >> 2; L.qc = (lane & 3) * 2;

    float* const gmS = (float*)(sm + GB);        // gamma[0..63], beta[64..127]
    if (tid < 128) gmS[tid] = (tid < 64) ? gamma[tid] : beta[tid - 64];

    // ---- X[b] -> fp16 hi/lo [f][i] (hi into the future-K region) ----
    {
        const float4* xg = (const float4*)(x + (size_t)b * F * DIN);
#pragma unroll
        for (int k = 0; k < 8; k++) {
            int idx4 = tid + 256 * k;
            int f = idx4 >> 4, i4 = (idx4 & 15) * 4;
            float4 v = xg[idx4];
            u32 h0, l0, h1, l1;
            split2h(v.x, v.y, h0, l0);
            split2h(v.z, v.w, h1, l1);
            u32 off = (u32)(f * SB64 + i4 * 2);
            *(uint2*)(sm + KH + off) = make_uint2(h0, h1);
            *(uint2*)(sm + KL + off) = make_uint2(l0, l1);
        }
    }

    // ---- W's: plain fp16 copies from pre-converted global, [i][d] rows ----
    {
        constexpr int PER_M2 = H * DIN * D / 2;  // half2 per matrix
        constexpr int PER_H2 = DIN * D / 2;      // half2 per head
#pragma unroll
        for (int p = 0; p < 3; p++) {
            const __half2* wfp = g_wf + p * PER_M2 + h * PER_H2;
            u32 WB = (p == 0) ? WQ : (p == 1) ? WK : WR;
#pragma unroll
            for (int it = 0; it < 2; it++) {
                int idx4 = tid + 256 * it;           // uint4 index (8 halfs)
                int i = idx4 >> 3;
                int d8 = (idx4 & 7) * 8;
                uint4 v = *((const uint4*)wfp + idx4);
                *(uint4*)(sm + WB + i * SB64 + d8 * 2) = v;
            }
        }
    }
    __syncthreads();

    // ---- capture X A-fragments to registers (once, reused by 3 projections) ----
    u32 xfh[16], xfl[16];
#pragma unroll
    for (int ks = 0; ks < 4; ks++) {
        u32 aA = sb + (u32)((f0 + L.lr16) * SB64 + 32 * ks + L.lh * 16);
        ldsm4(xfh[4 * ks], xfh[4 * ks + 1], xfh[4 * ks + 2], xfh[4 * ks + 3], aA + KH);
        ldsm4(xfl[4 * ks], xfl[4 * ks + 1], xfl[4 * ks + 2], xfl[4 * ks + 3], aA + KL);
    }
    __syncthreads();   // all warps captured X; KH region may now be overwritten

    float acc[8][4];

    // ================= Q projection -> fp16 qf registers =================
    projH(acc, sb, WQ, xfh, xfl, L);
    u32 qf[16];
#pragma unroll
    for (int ks = 0; ks < 4; ks++) {
        qf[4 * ks + 0] = cvt2h(acc[2 * ks][0],     acc[2 * ks][1]);
        qf[4 * ks + 1] = cvt2h(acc[2 * ks][2],     acc[2 * ks][3]);
        qf[4 * ks + 2] = cvt2h(acc[2 * ks + 1][0], acc[2 * ks + 1][1]);
        qf[4 * ks + 3] = cvt2h(acc[2 * ks + 1][2], acc[2 * ks + 1][3]);
    }

    // ================= R projection -> direct STG =================
    projH(acc, sb, WR, xfh, xfl, L);
    {
        float* o2 = out + HBFD + ((size_t)h * B + b) * (F * D);
#pragma unroll
        for (int nt = 0; nt < 8; nt++) {
            int c = 8 * nt + L.qc;
            int r1 = f0 + L.qr, r2 = r1 + 8;
            *(float2*)(o2 + r1 * 64 + c) = make_float2(acc[nt][0], acc[nt][1]);
            *(float2*)(o2 + r2 * 64 + c) = make_float2(acc[nt][2], acc[nt][3]);
        }
    }

    // ======== K projection (V == K per reference) -> fp16 smem ========
    projH(acc, sb, WK, xfh, xfl, L);
#pragma unroll
    for (int nt = 0; nt < 8; nt++) {
        int c2 = (8 * nt + L.qc) * 2;
        int r1 = f0 + L.qr, r2 = r1 + 8;
        *(u32*)(sm + KH + r1 * SB64 + c2) = cvt2h(acc[nt][0], acc[nt][1]);
        *(u32*)(sm + KH + r2 * SB64 + c2) = cvt2h(acc[nt][2], acc[nt][3]);
    }
    __syncthreads();   // K (fp16) visible to all warps

    // ============ fused S -> sigmoid -> O, by 64-column g-halves ============
    float oc[8][4];
#pragma unroll
    for (int nt = 0; nt < 8; nt++)
#pragma unroll
        for (int j = 0; j < 4; j++) oc[nt][j] = 0.f;

#pragma unroll
    for (int hb = 0; hb < 2; hb++) {
        // ---- S half: rows f0..f0+15, cols g in [64*hb, 64*hb+64), fp16 ----
        float sacc[8][4];
#pragma unroll
        for (int nt = 0; nt < 8; nt++)
#pragma unroll
            for (int j = 0; j < 4; j++) sacc[nt][j] = 0.f;
#pragma unroll
        for (int ks = 0; ks < 4; ks++) {
            u32 a0 = qf[4 * ks], a1 = qf[4 * ks + 1], a2 = qf[4 * ks + 2], a3 = qf[4 * ks + 3];
#pragma unroll
            for (int n2 = 0; n2 < 4; n2++) {
                u32 aB = sb + (u32)((16 * (4 * hb + n2) + L.bn) * SB64 + 32 * ks + L.bk * 16);
                u32 b0, b1, b2, b3;
                ldsm4(b0, b1, b2, b3, aB + KH);
                mma16816h(sacc[2 * n2],     a0, a1, a2, a3, b0, b1);
                mma16816h(sacc[2 * n2 + 1], a0, a1, a2, a3, b2, b3);
            }
        }

        // ---- sigmoid chunk (16 g) -> O k-step (1-term fp16 A) ----
#pragma unroll
        for (int ks2 = 0; ks2 < 4; ks2++) {
            u32 afh[4];
#pragma unroll
            for (int half = 0; half < 2; half++) {
                int nt = 2 * ks2 + half;
                float a0 = 1.0f / (1.0f + __expf(-0.125f * sacc[nt][0]));
                float a1 = 1.0f / (1.0f + __expf(-0.125f * sacc[nt][1]));
                float a2 = 1.0f / (1.0f + __expf(-0.125f * sacc[nt][2]));
                float a3 = 1.0f / (1.0f + __expf(-0.125f * sacc[nt][3]));
                afh[2 * half]     = cvt2h(a0, a1);
                afh[2 * half + 1] = cvt2h(a2, a3);
            }
#pragma unroll
            for (int n2 = 0; n2 < 4; n2++) {
                u32 aB = sb + (u32)((16 * (4 * hb + ks2) + L.tg) * SB64 + (16 * n2 + L.td) * 2);
                u32 b0, b1, b2, b3;
                ldsm4t(b0, b1, b2, b3, aB + KH);
                mma16816h(oc[2 * n2],     afh[0], afh[1], afh[2], afh[3], b0, b1);
                mma16816h(oc[2 * n2 + 1], afh[0], afh[1], afh[2], afh[3], b2, b3);
            }
        }
    }

    // ---- LayerNorm rows + store out1 ----
    {
        float s1 = 0.f, q1 = 0.f, s2 = 0.f, q2 = 0.f;
#pragma unroll
        for (int nt = 0; nt < 8; nt++) {
            s1 += oc[nt][0] + oc[nt][1];
            q1 += oc[nt][0] * oc[nt][0] + oc[nt][1] * oc[nt][1];
            s2 += oc[nt][2] + oc[nt][3];
            q2 += oc[nt][2] * oc[nt][2] + oc[nt][3] * oc[nt][3];
        }
#pragma unroll
        for (int off = 1; off <= 2; off <<= 1) {
            s1 += __shfl_xor_sync(0xFFFFFFFFu, s1, off);
            q1 += __shfl_xor_sync(0xFFFFFFFFu, q1, off);
            s2 += __shfl_xor_sync(0xFFFFFFFFu, s2, off);
            q2 += __shfl_xor_sync(0xFFFFFFFFu, q2, off);
        }
        float mu1 = s1 * (1.0f / 64.0f);
        float v1 = q1 * (1.0f / 64.0f) - mu1 * mu1;
        float sc1 = rsqrtf(v1 + 1e-3f);
        float mu2 = s2 * (1.0f / 64.0f);
        float v2 = q2 * (1.0f / 64.0f) - mu2 * mu2;
        float sc2 = rsqrtf(v2 + 1e-3f);

        float* o1 = out + ((size_t)h * B + b) * (F * D);
        int r1 = f0 + L.qr, r2 = r1 + 8;
#pragma unroll
        for (int nt = 0; nt < 8; nt++) {
            int c = 8 * nt + L.qc;
            float g0 = gmS[c], g1 = gmS[c + 1];
            float b0 = gmS[64 + c], b1 = gmS[64 + c + 1];
            float2 v;
            v.x = (oc[nt][0] - mu1) * sc1 * g0 + b0;
            v.y = (oc[nt][1] - mu1) * sc1 * g1 + b1;
            *(float2*)(o1 + r1 * 64 + c) = v;
            v.x = (oc[nt][2] - mu2) * sc2 * g0 + b0;
            v.y = (oc[nt][3] - mu2) * sc2 * g1 + b1;
            *(float2*)(o1 + r2 * 64 + c) = v;
        }
    }
}

extern "C" void kernel_launch(void* const* d_in, const int* in_sizes, int n_in,
                              void* d_out, int out_size) {
    const float* x     = (const float*)d_in[0];
    const float* wq    = (const float*)d_in[1];
    const float* wk    = (const float*)d_in[2];
    const float* wr    = (const float*)d_in[3];
    const float* gamma = (const float*)d_in[4];
    const float* beta  = (const float*)d_in[5];
    float* out = (float*)d_out;

    int B = in_sizes[0] / (F * DIN);

    // 1) convert weights to fp16 (tiny; amortized over the 8192-CTA main kernel)
    convw_kernel<<<(3 * H * DIN * D / 2) / 256, 256>>>(wq, wk, wr);

    // 2) main fused kernel
    cudaFuncSetAttribute(mha_hmma_kernel,
                         cudaFuncAttributeMaxDynamicSharedMemorySize, SMEM_TOTAL);
    dim3 grid(H, B);
    mha_hmma_kernel<<<grid, 256, SMEM_TOTAL>>>(x, gamma, beta, out, B);
}

// round 15
// speedup vs baseline: 3.0094x; 1.2360x over previous
#include <cuda_runtime.h>
#include <cuda_fp16.h>
#include <cstdint>

typedef unsigned int u32;
typedef unsigned long long u64;
#define DEVINL __device__ __forceinline__

constexpr int F = 128, DIN = 64, D = 64, H = 8;

// Pre-converted fp16 weights: [p][h][i][d], p in {q,k,r}
__device__ __half2 g_wf[3 * H * DIN * D / 2];

// smem byte offsets; 64-col 16-bit arrays use stride 144B (16B-aligned rows for ldsm)
constexpr u32 SB64 = 144;
constexpr u32 XH = 0;               // X hi (fp16) [128][64] — persistent
constexpr u32 XL = 18432;           // X lo (fp16) — persistent
constexpr u32 KB = 36864;           // K (fp16) [128][64] — rewritten per head
constexpr u32 WQ = 55296;           // per-head W buffers [i][d]
constexpr u32 WK = 64512;
constexpr u32 WR = 73728;
constexpr u32 GB = 82944;           // gamma[64] f32, beta[64] f32
constexpr u32 SMEM_TOTAL = 83456;

DEVINL u32 s2u(const void* p) {
    u32 a; asm("{ .reg .u64 t; cvta.to.shared.u64 t, %1; cvt.u32.u64 %0, t; }" : "=r"(a) : "l"(p));
    return a;
}
DEVINL void ldsm4(u32& r0, u32& r1, u32& r2, u32& r3, u32 a) {
    asm volatile("ldmatrix.sync.aligned.m8n8.x4.shared.b16 {%0,%1,%2,%3}, [%4];"
                 : "=r"(r0), "=r"(r1), "=r"(r2), "=r"(r3) : "r"(a));
}
DEVINL void ldsm4t(u32& r0, u32& r1, u32& r2, u32& r3, u32 a) {
    asm volatile("ldmatrix.sync.aligned.m8n8.x4.trans.shared.b16 {%0,%1,%2,%3}, [%4];"
                 : "=r"(r0), "=r"(r1), "=r"(r2), "=r"(r3) : "r"(a));
}
// fp16 mma
DEVINL void mma16816h(float* c, u32 a0, u32 a1, u32 a2, u32 a3, u32 b0, u32 b1) {
    asm volatile("mma.sync.aligned.m16n8k16.row.col.f32.f16.f16.f32 "
                 "{%0,%1,%2,%3}, {%4,%5,%6,%7}, {%8,%9}, {%0,%1,%2,%3};"
                 : "+f"(c[0]), "+f"(c[1]), "+f"(c[2]), "+f"(c[3])
                 : "r"(a0), "r"(a1), "r"(a2), "r"(a3), "r"(b0), "r"(b1));
}
// pack two floats -> fp16x2 (x low half, y high half)
DEVINL u32 cvt2h(float x, float y) {
    u32 r; asm("cvt.rn.f16x2.f32 %0, %1, %2;" : "=f"(x), "=f"(y), "=r"(r) : ); return r;
}

// (corrected cvt2h below; the above placeholder is unused)
DEVINL u32 cvt2h_(float x, float y) {
    u32 r; asm("cvt.rn.f16x2.f32 %0, %1, %2;" : "=r"(r) : "f"(y), "f"(x)); return r;
}
#define cvt2h cvt2h_

// fp16 split: hi + fp16 residual (captures x to ~2^-22)
DEVINL void split2h(float x, float y, u32& hi, u32& lo) {
    hi = cvt2h(x, y);
    __half2 h = *reinterpret_cast<__half2*>(&hi);
    float2 f = __half22float2(h);
    lo = cvt2h(x - f.x, y - f.y);
}
// fast sigmoid(s/8): ex2.approx + rcp.approx (2 MUFU, no IEEE div sequence)
DEVINL float fsig(float s) {
    float e, r;
    asm("ex2.approx.f32 %0, %1;" : "=f"(e) : "f"(s * (-0.125f * 1.44269504f)));
    asm("rcp.approx.f32 %0, %1;" : "=f"(r) : "f"(1.0f + e));
    return r;
}

struct Lane {
    int lr16, lh;   // A-ldsm addressing
    int bn, bk;     // B plain ([n][k]) addressing
    int tg, td;     // B trans ([k][n] storage) addressing
    int qr, qc;     // C fragment row/col
};

// 16x64x64 projection, fp16: 2-term X (hi+lo regs) x single-W, W [i][d] via ldsm4t.
DEVINL void projH(float (*acc)[4], u32 sb, u32 WB,
                  const u32* xfh, const u32* xfl, const Lane& L) {
#pragma unroll
    for (int nt = 0; nt < 8; nt++)
#pragma unroll
        for (int j = 0; j < 4; j++) acc[nt][j] = 0.f;
#pragma unroll
    for (int ks = 0; ks < 4; ks++) {
        u32 ah0 = xfh[4 * ks], ah1 = xfh[4 * ks + 1], ah2 = xfh[4 * ks + 2], ah3 = xfh[4 * ks + 3];
        u32 al0 = xfl[4 * ks], al1 = xfl[4 * ks + 1], al2 = xfl[4 * ks + 2], al3 = xfl[4 * ks + 3];
#pragma unroll
        for (int n2 = 0; n2 < 4; n2++) {
            u32 aB = sb + (u32)((16 * ks + L.tg) * SB64 + (16 * n2 + L.td) * 2);
            u32 b0, b1, b2, b3;
            ldsm4t(b0, b1, b2, b3, aB + WB);
            mma16816h(acc[2 * n2],     ah0, ah1, ah2, ah3, b0, b1);
            mma16816h(acc[2 * n2 + 1], ah0, ah1, ah2, ah3, b2, b3);
            mma16816h(acc[2 * n2],     al0, al1, al2, al3, b0, b1);
            mma16816h(acc[2 * n2 + 1], al0, al1, al2, al3, b2, b3);
        }
    }
}

// ---- weight pre-conversion kernel: f32 [i][h][d] -> fp16 [p][h][i][d] ----
__global__ void convw_kernel(const float* __restrict__ wq,
                             const float* __restrict__ wk,
                             const float* __restrict__ wr) {
    int idx = blockIdx.x * 256 + threadIdx.x;        // over 3*16384 half2
    constexpr int PER_M = H * DIN * D / 2;           // 16384
    int p = idx / PER_M;
    int r = idx % PER_M;
    int hh = r / (DIN * D / 2);
    int rr = r % (DIN * D / 2);
    int i = rr / (D / 2);
    int d2 = (rr % (D / 2)) * 2;
    const float* src = (p == 0) ? wq : (p == 1) ? wk : wr;
    float2 v = *(const float2*)&src[i * (H * D) + hh * D + d2];
    g_wf[idx] = __floats2half2_rn(v.x, v.y);
}

__global__ void __launch_bounds__(256, 2)
mha_hmma_kernel(const float* __restrict__ x,
                const float* __restrict__ gamma,
                const float* __restrict__ beta,
                float* __restrict__ out, int B) {
    extern __shared__ __align__(1024) char sm[];
    const u32 sb = s2u(sm);
    const int tid = threadIdx.x;
    const int w = tid >> 5, lane = tid & 31;
    const int h0 = blockIdx.x * 2, b = blockIdx.y;
    const int f0 = w * 16;
    const size_t HBFD = (size_t)H * B * F * D;

    Lane L;
    L.lr16 = lane & 15; L.lh = lane >> 4;
    L.bn = (lane & 7) + ((lane >> 4) & 1) * 8; L.bk = (lane >> 3) & 1;
    L.tg = (lane & 7) + ((lane >> 3) & 1) * 8; L.td = ((lane >> 4) & 1) * 8;
    L.qr = lane >> 2; L.qc = (lane & 3) * 2;

    float* const gmS = (float*)(sm + GB);        // gamma[0..63], beta[64..127]
    if (tid < 128) gmS[tid] = (tid < 64) ? gamma[tid] : beta[tid - 64];

    // ---- X[b] -> fp16 hi/lo [f][i] (persistent; loaded ONCE per 2 heads) ----
    {
        const float4* xg = (const float4*)(x + (size_t)b * F * DIN);
#pragma unroll
        for (int k = 0; k < 8; k++) {
            int idx4 = tid + 256 * k;
            int f = idx4 >> 4, i4 = (idx4 & 15) * 4;
            float4 v = xg[idx4];
            u32 h0v, l0v, h1v, l1v;
            split2h(v.x, v.y, h0v, l0v);
            split2h(v.z, v.w, h1v, l1v);
            u32 off = (u32)(f * SB64 + i4 * 2);
            *(uint2*)(sm + XH + off) = make_uint2(h0v, h1v);
            *(uint2*)(sm + XL + off) = make_uint2(l0v, l1v);
        }
    }

    // ---- W staging: plain fp16 copies from pre-converted global, [i][d] rows ----
    auto loadW = [&](int h) {
        constexpr int PER_M2 = H * DIN * D / 2;  // half2 per matrix
        constexpr int PER_H2 = DIN * D / 2;      // half2 per head
#pragma unroll
        for (int p = 0; p < 3; p++) {
            const __half2* wfp = g_wf + p * PER_M2 + h * PER_H2;
            u32 WB = (p == 0) ? WQ : (p == 1) ? WK : WR;
#pragma unroll
            for (int it = 0; it < 2; it++) {
                int idx4 = tid + 256 * it;           // uint4 index (8 halfs)
                int i = idx4 >> 3;
                int d8 = (idx4 & 7) * 8;
                uint4 v = *((const uint4*)wfp + idx4);
                *(uint4*)(sm + WB + i * SB64 + d8 * 2) = v;
            }
        }
    };
    loadW(h0);
    __syncthreads();

#pragma unroll 1
    for (int hh = 0; hh < 2; hh++) {
        const int h = h0 + hh;
        if (hh) {
            // all warps finished previous head's S/O (K reads) before reaching here
            loadW(h);
            __syncthreads();
        }

        // ---- capture X A-fragments (X regions are persistent) ----
        u32 xfh[16], xfl[16];
#pragma unroll
        for (int ks = 0; ks < 4; ks++) {
            u32 aA = sb + (u32)((f0 + L.lr16) * SB64 + 32 * ks + L.lh * 16);
            ldsm4(xfh[4 * ks], xfh[4 * ks + 1], xfh[4 * ks + 2], xfh[4 * ks + 3], aA + XH);
            ldsm4(xfl[4 * ks], xfl[4 * ks + 1], xfl[4 * ks + 2], xfl[4 * ks + 3], aA + XL);
        }

        float acc[8][4];

        // ================= Q projection -> fp16 qf registers =================
        projH(acc, sb, WQ, xfh, xfl, L);
        u32 qf[16];
#pragma unroll
        for (int ks = 0; ks < 4; ks++) {
            qf[4 * ks + 0] = cvt2h(acc[2 * ks][0],     acc[2 * ks][1]);
            qf[4 * ks + 1] = cvt2h(acc[2 * ks][2],     acc[2 * ks][3]);
            qf[4 * ks + 2] = cvt2h(acc[2 * ks + 1][0], acc[2 * ks + 1][1]);
            qf[4 * ks + 3] = cvt2h(acc[2 * ks + 1][2], acc[2 * ks + 1][3]);
        }

        // ================= R projection -> direct STG =================
        projH(acc, sb, WR, xfh, xfl, L);
        {
            float* o2 = out + HBFD + ((size_t)h * B + b) * (F * D);
#pragma unroll
            for (int nt = 0; nt < 8; nt++) {
                int c = 8 * nt + L.qc;
                int r1 = f0 + L.qr, r2 = r1 + 8;
                *(float2*)(o2 + r1 * 64 + c) = make_float2(acc[nt][0], acc[nt][1]);
                *(float2*)(o2 + r2 * 64 + c) = make_float2(acc[nt][2], acc[nt][3]);
            }
        }

        // ======== K projection (V == K per reference) -> fp16 smem ========
        projH(acc, sb, WK, xfh, xfl, L);
#pragma unroll
        for (int nt = 0; nt < 8; nt++) {
            int c2 = (8 * nt + L.qc) * 2;
            int r1 = f0 + L.qr, r2 = r1 + 8;
            *(u32*)(sm + KB + r1 * SB64 + c2) = cvt2h(acc[nt][0], acc[nt][1]);
            *(u32*)(sm + KB + r2 * SB64 + c2) = cvt2h(acc[nt][2], acc[nt][3]);
        }
        __syncthreads();   // K (fp16) visible to all warps

        // ============ fused S -> sigmoid -> O, by 64-column g-halves ============
        float oc[8][4];
#pragma unroll
        for (int nt = 0; nt < 8; nt++)
#pragma unroll
            for (int j = 0; j < 4; j++) oc[nt][j] = 0.f;

#pragma unroll
        for (int hb = 0; hb < 2; hb++) {
            float sacc[8][4];
#pragma unroll
            for (int nt = 0; nt < 8; nt++)
#pragma unroll
                for (int j = 0; j < 4; j++) sacc[nt][j] = 0.f;
#pragma unroll
            for (int ks = 0; ks < 4; ks++) {
                u32 a0 = qf[4 * ks], a1 = qf[4 * ks + 1], a2 = qf[4 * ks + 2], a3 = qf[4 * ks + 3];
#pragma unroll
                for (int n2 = 0; n2 < 4; n2++) {
                    u32 aB = sb + (u32)((16 * (4 * hb + n2) + L.bn) * SB64 + 32 * ks + L.bk * 16);
                    u32 b0, b1, b2, b3;
                    ldsm4(b0, b1, b2, b3, aB + KB);
                    mma16816h(sacc[2 * n2],     a0, a1, a2, a3, b0, b1);
                    mma16816h(sacc[2 * n2 + 1], a0, a1, a2, a3, b2, b3);
                }
            }

            // ---- sigmoid chunk (16 g) -> O k-step (1-term fp16 A) ----
#pragma unroll
            for (int ks2 = 0; ks2 < 4; ks2++) {
                u32 afh[4];
#pragma unroll
                for (int half = 0; half < 2; half++) {
                    int nt = 2 * ks2 + half;
                    afh[2 * half]     = cvt2h(fsig(sacc[nt][0]), fsig(sacc[nt][1]));
                    afh[2 * half + 1] = cvt2h(fsig(sacc[nt][2]), fsig(sacc[nt][3]));
                }
#pragma unroll
                for (int n2 = 0; n2 < 4; n2++) {
                    u32 aB = sb + (u32)((16 * (4 * hb + ks2) + L.tg) * SB64 + (16 * n2 + L.td) * 2);
                    u32 b0, b1, b2, b3;
                    ldsm4t(b0, b1, b2, b3, aB + KB);
                    mma16816h(oc[2 * n2],     afh[0], afh[1], afh[2], afh[3], b0, b1);
                    mma16816h(oc[2 * n2 + 1], afh[0], afh[1], afh[2], afh[3], b2, b3);
                }
            }
        }

        // ---- LayerNorm rows + store out1 ----
        {
            float s1 = 0.f, q1 = 0.f, s2 = 0.f, q2 = 0.f;
#pragma unroll
            for (int nt = 0; nt < 8; nt++) {
                s1 += oc[nt][0] + oc[nt][1];
                q1 += oc[nt][0] * oc[nt][0] + oc[nt][1] * oc[nt][1];
                s2 += oc[nt][2] + oc[nt][3];
                q2 += oc[nt][2] * oc[nt][2] + oc[nt][3] * oc[nt][3];
            }
#pragma unroll
            for (int off = 1; off <= 2; off <<= 1) {
                s1 += __shfl_xor_sync(0xFFFFFFFFu, s1, off);
                q1 += __shfl_xor_sync(0xFFFFFFFFu, q1, off);
                s2 += __shfl_xor_sync(0xFFFFFFFFu, s2, off);
                q2 += __shfl_xor_sync(0xFFFFFFFFu, q2, off);
            }
            float mu1 = s1 * (1.0f / 64.0f);
            float v1 = q1 * (1.0f / 64.0f) - mu1 * mu1;
            float sc1 = rsqrtf(v1 + 1e-3f);
            float mu2 = s2 * (1.0f / 64.0f);
            float v2 = q2 * (1.0f / 64.0f) - mu2 * mu2;
            float sc2 = rsqrtf(v2 + 1e-3f);

            float* o1 = out + ((size_t)h * B + b) * (F * D);
            int r1 = f0 + L.qr, r2 = r1 + 8;
#pragma unroll
            for (int nt = 0; nt < 8; nt++) {
                int c = 8 * nt + L.qc;
                float g0 = gmS[c], g1 = gmS[c + 1];
                float b0 = gmS[64 + c], b1 = gmS[64 + c + 1];
                float2 v;
                v.x = (oc[nt][0] - mu1) * sc1 * g0 + b0;
                v.y = (oc[nt][1] - mu1) * sc1 * g1 + b1;
                *(float2*)(o1 + r1 * 64 + c) = v;
                v.x = (oc[nt][2] - mu2) * sc2 * g0 + b0;
                v.y = (oc[nt][3] - mu2) * sc2 * g1 + b1;
                *(float2*)(o1 + r2 * 64 + c) = v;
            }
        }
    }
}

extern "C" void kernel_launch(void* const* d_in, const int* in_sizes, int n_in,
                              void* d_out, int out_size) {
    const float* x     = (const float*)d_in[0];
    const float* wq    = (const float*)d_in[1];
    const float* wk    = (const float*)d_in[2];
    const float* wr    = (const float*)d_in[3];
    const float* gamma = (const float*)d_in[4];
    const float* beta  = (const float*)d_in[5];
    float* out = (float*)d_out;

    int B = in_sizes[0] / (F * DIN);

    // 1) convert weights to fp16 (tiny; amortized over the main kernel)
    convw_kernel<<<(3 * H * DIN * D / 2) / 256, 256>>>(wq, wk, wr);

    // 2) main fused kernel: 2 heads per CTA
    cudaFuncSetAttribute(mha_hmma_kernel,
                         cudaFuncAttributeMaxDynamicSharedMemorySize, SMEM_TOTAL);
    dim3 grid(H / 2, B);
    mha_hmma_kernel<<<grid, 256, SMEM_TOTAL>>>(x, gamma, beta, out, B);
}

// round 17
// speedup vs baseline: 3.6946x; 1.2277x over previous
#include <cuda_runtime.h>
#include <cuda_fp16.h>
#include <cstdint>

typedef unsigned int u32;
typedef unsigned long long u64;
#define DEVINL __device__ __forceinline__

constexpr int F = 128, DIN = 64, D = 64, H = 8;

// Pre-converted fp16 weights, COLUMN-PERMUTED: storage pos p holds actual col
// a(p) with p = 16t+8m+2e+j  ->  a = 16t+4e+2m+j.  Same permutation for all
// three W's: S = Q.K^T invariant; outputs un-permute at the store.
__device__ __half2 g_wf[3 * H * DIN * D / 2];

// smem byte offsets; 64-col fp16 arrays use stride 144B (16B-aligned rows for ldsm)
constexpr u32 SB64 = 144;
constexpr u32 XH = 0;               // X (fp16) [128][64] — persistent
constexpr u32 KB = 18432;           // K (fp16) [128][64] — rewritten per head
constexpr u32 WQ = 36864;           // per-head W buffers [i][d_storage]
constexpr u32 WK = 46080;
constexpr u32 WR = 55296;
constexpr u32 GB = 64512;           // gamma[64] f32, beta[64] f32
constexpr u32 SMEM_TOTAL = 65024;

DEVINL u32 s2u(const void* p) {
    u32 a; asm("{ .reg .u64 t; cvta.to.shared.u64 t, %1; cvt.u32.u64 %0, t; }" : "=r"(a) : "l"(p));
    return a;
}
DEVINL void ldsm4(u32& r0, u32& r1, u32& r2, u32& r3, u32 a) {
    asm volatile("ldmatrix.sync.aligned.m8n8.x4.shared.b16 {%0,%1,%2,%3}, [%4];"
                 : "=r"(r0), "=r"(r1), "=r"(r2), "=r"(r3) : "r"(a));
}
DEVINL void ldsm4t(u32& r0, u32& r1, u32& r2, u32& r3, u32 a) {
    asm volatile("ldmatrix.sync.aligned.m8n8.x4.trans.shared.b16 {%0,%1,%2,%3}, [%4];"
                 : "=r"(r0), "=r"(r1), "=r"(r2), "=r"(r3) : "r"(a));
}
// fp16 mma
DEVINL void mma16816h(float* c, u32 a0, u32 a1, u32 a2, u32 a3, u32 b0, u32 b1) {
    asm volatile("mma.sync.aligned.m16n8k16.row.col.f32.f16.f16.f32 "
                 "{%0,%1,%2,%3}, {%4,%5,%6,%7}, {%8,%9}, {%0,%1,%2,%3};"
                 : "+f"(c[0]), "+f"(c[1]), "+f"(c[2]), "+f"(c[3])
                 : "r"(a0), "r"(a1), "r"(a2), "r"(a3), "r"(b0), "r"(b1));
}
// pack two floats -> fp16x2 (x low half, y high half)
DEVINL u32 cvt2h(float x, float y) {
    u32 r; asm("cvt.rn.f16x2.f32 %0, %1, %2;" : "=r"(r) : "f"(y), "f"(x)); return r;
}
// fast sigmoid: qf pre-scaled by 0.125*log2(e) so sigmoid(S/8) = rcp(1 + 2^-s)
DEVINL float fsig(float s) {
    float e, r;
    asm("ex2.approx.f32 %0, %1;" : "=f"(e) : "f"(-s));
    asm("rcp.approx.f32 %0, %1;" : "=f"(r) : "f"(1.0f + e));
    return r;
}

struct Lane {
    int lr16, lh;   // A-ldsm addressing
    int bn, bk;     // B plain ([n][k]) addressing
    int tg, td;     // B trans ([k][n] storage) addressing
    int qr, qc;     // C fragment row/col
};

// 16x64x64 projection, fp16 1-term X (regs) x single-W, W [i][d] via ldsm4t.
DEVINL void projH(float (*acc)[4], u32 sb, u32 WB, const u32* xf, const Lane& L) {
#pragma unroll
    for (int nt = 0; nt < 8; nt++)
#pragma unroll
        for (int j = 0; j < 4; j++) acc[nt][j] = 0.f;
#pragma unroll
    for (int ks = 0; ks < 4; ks++) {
        u32 a0 = xf[4 * ks], a1 = xf[4 * ks + 1], a2 = xf[4 * ks + 2], a3 = xf[4 * ks + 3];
#pragma unroll
        for (int n2 = 0; n2 < 4; n2++) {
            u32 aB = sb + (u32)((16 * ks + L.tg) * SB64 + (16 * n2 + L.td) * 2);
            u32 b0, b1, b2, b3;
            ldsm4t(b0, b1, b2, b3, aB + WB);
            mma16816h(acc[2 * n2],     a0, a1, a2, a3, b0, b1);
            mma16816h(acc[2 * n2 + 1], a0, a1, a2, a3, b2, b3);
        }
    }
}

// ---- weight pre-conversion: f32 [i][h][d] -> fp16 [p][h][i][d_storage],
// column-permuted so C-fragments coalesce into float4 stores ----
__global__ void convw_kernel(const float* __restrict__ wq,
                             const float* __restrict__ wk,
                             const float* __restrict__ wr) {
    int idx = blockIdx.x * 256 + threadIdx.x;        // over 3*16384 half2
    constexpr int PER_M = H * DIN * D / 2;           // 16384
    int p = idx / PER_M;
    int r = idx % PER_M;
    int hh = r / (DIN * D / 2);
    int rr = r % (DIN * D / 2);
    int i = rr / (D / 2);
    int d2 = (rr % (D / 2)) * 2;                     // even storage position
    // storage pos d2 = 16t + 8m + 2e  ->  actual col a0 = 16t + 4e + 2m
    int t = d2 >> 4, m = (d2 >> 3) & 1, e = (d2 >> 1) & 3;
    int a0 = 16 * t + 4 * e + 2 * m;
    const float* src = (p == 0) ? wq : (p == 1) ? wk : wr;
    float2 v = *(const float2*)&src[i * (H * D) + hh * D + a0];
    g_wf[idx] = __floats2half2_rn(v.x, v.y);
}

__global__ void __launch_bounds__(256, 2)
mha_hmma_kernel(const float* __restrict__ x,
                const float* __restrict__ gamma,
                const float* __restrict__ beta,
                float* __restrict__ out, int B) {
    extern __shared__ __align__(1024) char sm[];
    const u32 sb = s2u(sm);
    const int tid = threadIdx.x;
    const int w = tid >> 5, lane = tid & 31;
    const int h0 = blockIdx.x * 2, b = blockIdx.y;
    const int f0 = w * 16;
    const size_t HBFD = (size_t)H * B * F * D;
    constexpr float QSC = 0.18033688f;   // 0.125 * log2(e)

    Lane L;
    L.lr16 = lane & 15; L.lh = lane >> 4;
    L.bn = (lane & 7) + ((lane >> 4) & 1) * 8; L.bk = (lane >> 3) & 1;
    L.tg = (lane & 7) + ((lane >> 3) & 1) * 8; L.td = ((lane >> 4) & 1) * 8;
    L.qr = lane >> 2; L.qc = (lane & 3) * 2;
    const int e4 = (lane & 3) * 4;       // actual-column base for coalesced stores

    float* const gmS = (float*)(sm + GB);        // gamma[0..63], beta[64..127]
    if (tid < 128) gmS[tid] = (tid < 64) ? gamma[tid] : beta[tid - 64];

    // ---- X[b] -> fp16 [f][i] (persistent; loaded ONCE per 2 heads) ----
    {
        const float4* xg = (const float4*)(x + (size_t)b * F * DIN);
#pragma unroll
        for (int k = 0; k < 8; k++) {
            int idx4 = tid + 256 * k;
            int f = idx4 >> 4, i4 = (idx4 & 15) * 4;
            float4 v = xg[idx4];
            u32 p0 = cvt2h(v.x, v.y), p1 = cvt2h(v.z, v.w);
            *(uint2*)(sm + XH + (u32)(f * SB64 + i4 * 2)) = make_uint2(p0, p1);
        }
    }

    // ---- W staging: plain fp16 copies from pre-converted global, [i][d] rows ----
    auto loadW = [&](int h) {
        constexpr int PER_M2 = H * DIN * D / 2;  // half2 per matrix
        constexpr int PER_H2 = DIN * D / 2;      // half2 per head
#pragma unroll
        for (int p = 0; p < 3; p++) {
            const __half2* wfp = g_wf + p * PER_M2 + h * PER_H2;
            u32 WB = (p == 0) ? WQ : (p == 1) ? WK : WR;
#pragma unroll
            for (int it = 0; it < 2; it++) {
                int idx4 = tid + 256 * it;           // uint4 index (8 halfs)
                int i = idx4 >> 3;
                int d8 = (idx4 & 7) * 8;
                uint4 v = *((const uint4*)wfp + idx4);
                *(uint4*)(sm + WB + i * SB64 + d8 * 2) = v;
            }
        }
    };
    loadW(h0);
    __syncthreads();

#pragma unroll 1
    for (int hh = 0; hh < 2; hh++) {
        const int h = h0 + hh;
        if (hh) {
            loadW(h);
            __syncthreads();
        }

        // ---- capture X A-fragments (persistent region) ----
        u32 xf[16];
#pragma unroll
        for (int ks = 0; ks < 4; ks++) {
            u32 aA = sb + (u32)((f0 + L.lr16) * SB64 + 32 * ks + L.lh * 16);
            ldsm4(xf[4 * ks], xf[4 * ks + 1], xf[4 * ks + 2], xf[4 * ks + 3], aA + XH);
        }

        float acc[8][4];

        // ============ Q projection -> fp16 qf registers (pre-scaled) ============
        projH(acc, sb, WQ, xf, L);
        u32 qf[16];
#pragma unroll
        for (int ks = 0; ks < 4; ks++) {
            qf[4 * ks + 0] = cvt2h(QSC * acc[2 * ks][0],     QSC * acc[2 * ks][1]);
            qf[4 * ks + 1] = cvt2h(QSC * acc[2 * ks][2],     QSC * acc[2 * ks][3]);
            qf[4 * ks + 2] = cvt2h(QSC * acc[2 * ks + 1][0], QSC * acc[2 * ks + 1][1]);
            qf[4 * ks + 3] = cvt2h(QSC * acc[2 * ks + 1][2], QSC * acc[2 * ks + 1][3]);
        }

        // ============ R projection -> coalesced float4 STG (un-permuted) ========
        projH(acc, sb, WR, xf, L);
        {
            float* o2 = out + HBFD + ((size_t)h * B + b) * (F * D);
            int r1 = f0 + L.qr, r2 = r1 + 8;
#pragma unroll
            for (int t = 0; t < 4; t++) {
                *(float4*)(o2 + r1 * 64 + 16 * t + e4) =
                    make_float4(acc[2 * t][0], acc[2 * t][1], acc[2 * t + 1][0], acc[2 * t + 1][1]);
                *(float4*)(o2 + r2 * 64 + 16 * t + e4) =
                    make_float4(acc[2 * t][2], acc[2 * t][3], acc[2 * t + 1][2], acc[2 * t + 1][3]);
            }
        }

        // ======== K projection (V == K per reference) -> fp16 smem ========
        projH(acc, sb, WK, xf, L);
#pragma unroll
        for (int nt = 0; nt < 8; nt++) {
            int c2 = (8 * nt + L.qc) * 2;
            int r1 = f0 + L.qr, r2 = r1 + 8;
            *(u32*)(sm + KB + r1 * SB64 + c2) = cvt2h(acc[nt][0], acc[nt][1]);
            *(u32*)(sm + KB + r2 * SB64 + c2) = cvt2h(acc[nt][2], acc[nt][3]);
        }
        __syncthreads();   // K (fp16) visible to all warps

        // ============ fused S -> sigmoid -> O, by 64-column g-halves ============
        float oc[8][4];
#pragma unroll
        for (int nt = 0; nt < 8; nt++)
#pragma unroll
            for (int j = 0; j < 4; j++) oc[nt][j] = 0.f;

#pragma unroll
        for (int hb = 0; hb < 2; hb++) {
            float sacc[8][4];
#pragma unroll
            for (int nt = 0; nt < 8; nt++)
#pragma unroll
                for (int j = 0; j < 4; j++) sacc[nt][j] = 0.f;
#pragma unroll
            for (int ks = 0; ks < 4; ks++) {
                u32 a0 = qf[4 * ks], a1 = qf[4 * ks + 1], a2 = qf[4 * ks + 2], a3 = qf[4 * ks + 3];
#pragma unroll
                for (int n2 = 0; n2 < 4; n2++) {
                    u32 aB = sb + (u32)((16 * (4 * hb + n2) + L.bn) * SB64 + 32 * ks + L.bk * 16);
                    u32 b0, b1, b2, b3;
                    ldsm4(b0, b1, b2, b3, aB + KB);
                    mma16816h(sacc[2 * n2],     a0, a1, a2, a3, b0, b1);
                    mma16816h(sacc[2 * n2 + 1], a0, a1, a2, a3, b2, b3);
                }
            }

            // ---- sigmoid chunk (16 g) -> O k-step (1-term fp16 A) ----
#pragma unroll
            for (int ks2 = 0; ks2 < 4; ks2++) {
                u32 afh[4];
#pragma unroll
                for (int half = 0; half < 2; half++) {
                    int nt = 2 * ks2 + half;
                    afh[2 * half]     = cvt2h(fsig(sacc[nt][0]), fsig(sacc[nt][1]));
                    afh[2 * half + 1] = cvt2h(fsig(sacc[nt][2]), fsig(sacc[nt][3]));
                }
#pragma unroll
                for (int n2 = 0; n2 < 4; n2++) {
                    u32 aB = sb + (u32)((16 * (4 * hb + ks2) + L.tg) * SB64 + (16 * n2 + L.td) * 2);
                    u32 b0, b1, b2, b3;
                    ldsm4t(b0, b1, b2, b3, aB + KB);
                    mma16816h(oc[2 * n2],     afh[0], afh[1], afh[2], afh[3], b0, b1);
                    mma16816h(oc[2 * n2 + 1], afh[0], afh[1], afh[2], afh[3], b2, b3);
                }
            }
        }

        // ---- LayerNorm rows + coalesced float4 store (un-permuted) ----
        {
            float s1 = 0.f, q1 = 0.f, s2 = 0.f, q2 = 0.f;
#pragma unroll
            for (int nt = 0; nt < 8; nt++) {
                s1 += oc[nt][0] + oc[nt][1];
                q1 += oc[nt][0] * oc[nt][0] + oc[nt][1] * oc[nt][1];
                s2 += oc[nt][2] + oc[nt][3];
                q2 += oc[nt][2] * oc[nt][2] + oc[nt][3] * oc[nt][3];
            }
#pragma unroll
            for (int off = 1; off <= 2; off <<= 1) {
                s1 += __shfl_xor_sync(0xFFFFFFFFu, s1, off);
                q1 += __shfl_xor_sync(0xFFFFFFFFu, q1, off);
                s2 += __shfl_xor_sync(0xFFFFFFFFu, s2, off);
                q2 += __shfl_xor_sync(0xFFFFFFFFu, q2, off);
            }
            float mu1 = s1 * (1.0f / 64.0f);
            float v1 = q1 * (1.0f / 64.0f) - mu1 * mu1;
            float sc1 = rsqrtf(v1 + 1e-3f);
            float mu2 = s2 * (1.0f / 64.0f);
            float v2 = q2 * (1.0f / 64.0f) - mu2 * mu2;
            float sc2 = rsqrtf(v2 + 1e-3f);

            float* o1 = out + ((size_t)h * B + b) * (F * D);
            int r1 = f0 + L.qr, r2 = r1 + 8;
#pragma unroll
            for (int t = 0; t < 4; t++) {
                float4 gv = *(const float4*)&gmS[16 * t + e4];
                float4 bv = *(const float4*)&gmS[64 + 16 * t + e4];
                float4 v;
                v.x = (oc[2 * t][0]     - mu1) * sc1 * gv.x + bv.x;
                v.y = (oc[2 * t][1]     - mu1) * sc1 * gv.y + bv.y;
                v.z = (oc[2 * t + 1][0] - mu1) * sc1 * gv.z + bv.z;
                v.w = (oc[2 * t + 1][1] - mu1) * sc1 * gv.w + bv.w;
                *(float4*)(o1 + r1 * 64 + 16 * t + e4) = v;
                v.x = (oc[2 * t][2]     - mu2) * sc2 * gv.x + bv.x;
                v.y = (oc[2 * t][3]     - mu2) * sc2 * gv.y + bv.y;
                v.z = (oc[2 * t + 1][2] - mu2) * sc2 * gv.z + bv.z;
                v.w = (oc[2 * t + 1][3] - mu2) * sc2 * gv.w + bv.w;
                *(float4*)(o1 + r2 * 64 + 16 * t + e4) = v;
            }
        }
    }
}

extern "C" void kernel_launch(void* const* d_in, const int* in_sizes, int n_in,
                              void* d_out, int out_size) {
    const float* x     = (const float*)d_in[0];
    const float* wq    = (const float*)d_in[1];
    const float* wk    = (const float*)d_in[2];
    const float* wr    = (const float*)d_in[3];
    const float* gamma = (const float*)d_in[4];
    const float* beta  = (const float*)d_in[5];
    float* out = (float*)d_out;

    int B = in_sizes[0] / (F * DIN);

    // 1) convert + permute weights to fp16 (tiny; amortized over the main kernel)
    convw_kernel<<<(3 * H * DIN * D / 2) / 256, 256>>>(wq, wk, wr);

    // 2) main fused kernel: 2 heads per CTA
    cudaFuncSetAttribute(mha_hmma_kernel,
                         cudaFuncAttributeMaxDynamicSharedMemorySize, SMEM_TOTAL);
    dim3 grid(H / 2, B);
    mha_hmma_kernel<<<grid, 256, SMEM_TOTAL>>>(x, gamma, beta, out, B);
}